// round 6
// baseline (speedup 1.0000x reference)
#include <cuda_runtime.h>
#include <cuda_fp16.h>
#include <mma.h>
#include <cstdint>
#include <cstddef>

using namespace nvcuda;

#define NN    8192
#define IND   256
#define HH    128
#define NL    3
#define NNET  3

// ---------------- device scratch (static, allowed) ----------------
__device__ __align__(16) __half g_A16[(size_t)NNET * NN * NN];   // 402 MB fp16 adj cache
__device__ __align__(16) __half g_X16[NN * IND];
__device__ __align__(16) __half g_Wi16[IND * HH];
__device__ __align__(16) __half g_Ws[NL * 2 * HH * HH];          // fused [Wu_top; Wm@Wu_bot]
__device__ float g_bc[NL * HH];                                   // fused bias
__device__ __align__(16) __half g_h016[NN * HH];
__device__ __align__(16) __half g_comb[NN * 2 * HH];             // [h | msg]
__device__ __align__(16) float g_ps[4 * NN * HH];                // split-K fp32 partials (16 MB)
__device__ float g_invdeg[NNET * NN];
__device__ float g_embs[(size_t)NNET * NN * HH];                 // per-net final layer embeddings
__device__ float g_part[128 * HH];

// ---------------- helpers ----------------
__device__ __forceinline__ uint32_t s2u(const void* p){
    uint32_t a;
    asm("{ .reg .u64 t; cvta.to.shared.u64 t, %1; cvt.u32.u64 %0, t; }" : "=r"(a) : "l"(p));
    return a;
}
__device__ __forceinline__ void cp16(uint32_t dst, const void* src){
    asm volatile("cp.async.cg.shared.global [%0], [%1], 16;" :: "r"(dst), "l"(src));
}
#define CP_COMMIT() asm volatile("cp.async.commit_group;" ::: "memory")
#define CP_WAIT1()  asm volatile("cp.async.wait_group 1;" ::: "memory")

// =================== pipelined SpMM: part = A[128-rows] @ B  (fp32 partials) ===================
// grid (64, 4): blockIdx.x = M tile (128 rows), blockIdx.y = K quarter (2048).
// 3-stage cp.async pipeline, BK=64, 8 warps each computing 32x64.
#define GB_S     3
#define GB_KSPL  2048
#define GB_ASZ   (128 * 72 * 2)                 // 18432 B
#define GB_BSZ   (64 * 136 * 2)                 // 17408 B
#define GB_STG   (GB_ASZ + GB_BSZ)              // 35840 B
#define GB_SMEM  (GB_S * GB_STG)                // 107520 B

__global__ __launch_bounds__(256, 1) void gemm_big(
    const __half* __restrict__ A,
    const __half* __restrict__ B, int ldb,
    float* __restrict__ part)
{
    extern __shared__ char dsm[];
    uint32_t sb = s2u(dsm);
    int tid = threadIdx.x;
    int wid = tid >> 5;
    int bm = blockIdx.x * 128;
    int kbase = blockIdx.y * GB_KSPL;
    int wm = (wid >> 1) * 32;
    int wn = (wid & 1) * 64;

    auto load_stage = [&](int st, int kt) {
        int k0 = kbase + kt * 64;
        uint32_t abase = sb + st * GB_STG;
        uint32_t bbase = abase + GB_ASZ;
#pragma unroll
        for (int i = 0; i < 4; i++) {
            int idx = tid + i * 256;
            int r = idx >> 3, c = idx & 7;
            cp16(abase + r * 144 + c * 16,
                 A + (size_t)(bm + r) * NN + k0 + c * 8);
        }
#pragma unroll
        for (int i = 0; i < 4; i++) {
            int idx = tid + i * 256;
            int r = idx >> 4, c = idx & 15;
            cp16(bbase + r * 272 + c * 16,
                 B + (size_t)(k0 + r) * ldb + c * 8);
        }
    };

    wmma::fragment<wmma::accumulator, 16, 16, 16, float> acc[2][4];
#pragma unroll
    for (int i = 0; i < 2; i++)
#pragma unroll
        for (int j = 0; j < 4; j++)
            wmma::fill_fragment(acc[i][j], 0.0f);

    load_stage(0, 0); CP_COMMIT();
    load_stage(1, 1); CP_COMMIT();

    const int nk = GB_KSPL / 64;
    int st_use = 0, st_load = 2;
    for (int kt = 0; kt < nk; kt++) {
        CP_WAIT1();
        __syncthreads();
        if (kt + 2 < nk) load_stage(st_load, kt + 2);
        CP_COMMIT();

        const __half* pA = reinterpret_cast<const __half*>(dsm + st_use * GB_STG);
        const __half* pB = reinterpret_cast<const __half*>(dsm + st_use * GB_STG + GB_ASZ);
#pragma unroll
        for (int kk = 0; kk < 64; kk += 16) {
            wmma::fragment<wmma::matrix_a, 16, 16, 16, __half, wmma::row_major> fa[2];
            wmma::fragment<wmma::matrix_b, 16, 16, 16, __half, wmma::row_major> fb[4];
#pragma unroll
            for (int i = 0; i < 2; i++)
                wmma::load_matrix_sync(fa[i], pA + (size_t)(wm + 16 * i) * 72 + kk, 72);
#pragma unroll
            for (int j = 0; j < 4; j++)
                wmma::load_matrix_sync(fb[j], pB + (size_t)kk * 136 + wn + 16 * j, 136);
#pragma unroll
            for (int i = 0; i < 2; i++)
#pragma unroll
                for (int j = 0; j < 4; j++)
                    wmma::mma_sync(acc[i][j], fa[i], fb[j], acc[i][j]);
        }
        __syncthreads();
        st_use = (st_use + 1) % GB_S;
        st_load = (st_load + 1) % GB_S;
    }

    // epilogue: stage accumulators to smem, vectorized fp32 store
    float* sC = reinterpret_cast<float*>(dsm);     // 128 x 132
#pragma unroll
    for (int i = 0; i < 2; i++)
#pragma unroll
        for (int j = 0; j < 4; j++)
            wmma::store_matrix_sync(sC + (size_t)(wm + 16 * i) * 132 + wn + 16 * j,
                                    acc[i][j], 132, wmma::mem_row_major);
    __syncthreads();

    float* out = part + (size_t)blockIdx.y * NN * HH + (size_t)bm * HH;
    for (int e = tid; e < 128 * 128 / 4; e += 256) {
        int r = e >> 5, c = (e & 31) * 4;
        *reinterpret_cast<float4*>(out + (size_t)r * HH + c) =
            *reinterpret_cast<const float4*>(sC + (size_t)r * 132 + c);
    }
}

// ------- combine 4 split-K partials: comb[:,128:256] = (p0+p1+p2+p3)*invdeg (fp16) -------
__global__ void combine_k(const float* __restrict__ inv)
{
    int i = blockIdx.x * 256 + threadIdx.x;       // float4 group, 0..262143
    const float4* p = reinterpret_cast<const float4*>(g_ps);
    float4 a = p[i];
    float4 b = p[i + NN * HH / 4];
    float4 c = p[i + 2 * (NN * HH / 4)];
    float4 d = p[i + 3 * (NN * HH / 4)];
    float s = inv[i >> 5];
    float x0 = ((a.x + b.x) + c.x + d.x) * s;
    float x1 = ((a.y + b.y) + c.y + d.y) * s;
    float x2 = ((a.z + b.z) + c.z + d.z) * s;
    float x3 = ((a.w + b.w) + c.w + d.w) * s;
    __half2 h0 = __floats2half2_rn(x0, x1);
    __half2 h1 = __floats2half2_rn(x2, x3);
    uint2 u;
    u.x = *reinterpret_cast<unsigned*>(&h0);
    u.y = *reinterpret_cast<unsigned*>(&h1);
    int n = i >> 5, coff = (i & 31) * 4;
    *reinterpret_cast<uint2*>(g_comb + (size_t)n * 256 + 128 + coff) = u;
}

// ---------------- adj fp32 -> fp16 + row-sum (one pass) ----------------
__global__ void prep_adj(const float* __restrict__ adj)
{
    size_t row = blockIdx.x;
    const float* src = adj + row * NN;
    __half* dst = g_A16 + row * NN;
    int t = threadIdx.x;
    float s = 0.f;
#pragma unroll
    for (int i = 0; i < 8; i++) {
        int v4 = t + i * 256;
        float4 f = *reinterpret_cast<const float4*>(src + (size_t)v4 * 4);
        s += f.x + f.y + f.z + f.w;
        __half2 h0 = __floats2half2_rn(f.x, f.y);
        __half2 h1 = __floats2half2_rn(f.z, f.w);
        uint2 u;
        u.x = *reinterpret_cast<unsigned*>(&h0);
        u.y = *reinterpret_cast<unsigned*>(&h1);
        *reinterpret_cast<uint2*>(dst + (size_t)v4 * 4) = u;
    }
#pragma unroll
    for (int o = 16; o; o >>= 1) s += __shfl_xor_sync(0xFFFFFFFFu, s, o);
    __shared__ float ws[8];
    int wid = t >> 5, lane = t & 31;
    if (lane == 0) ws[wid] = s;
    __syncthreads();
    if (t == 0) {
        float tot = 0.f;
#pragma unroll
        for (int i = 0; i < 8; i++) tot += ws[i];
        g_invdeg[row] = 1.0f / fmaxf(tot, 1.0f);
    }
}

// ---------------- generic fp32 -> fp16 convert ----------------
__global__ void f2h(const float* __restrict__ src, __half* __restrict__ dst, int n4)
{
    int i = blockIdx.x * blockDim.x + threadIdx.x;
    if (i < n4) {
        float4 f = reinterpret_cast<const float4*>(src)[i];
        __half2 a = __floats2half2_rn(f.x, f.y);
        __half2 b = __floats2half2_rn(f.z, f.w);
        uint2 u;
        u.x = *reinterpret_cast<unsigned*>(&a);
        u.y = *reinterpret_cast<unsigned*>(&b);
        *reinterpret_cast<uint2*>(dst + (size_t)i * 4) = u;
    }
}

// ------- fused weight precompute: Ws[l] = [Wu_top ; Wm[l]@Wu_bot], bc[l] = bm@Wu_bot + bu -------
__global__ void fuse_w(const float* __restrict__ Wm, const float* __restrict__ Wu,
                       const float* __restrict__ bm, const float* __restrict__ bu)
{
    int l = blockIdx.y;
    int r = blockIdx.x;          // 0..256
    int j = threadIdx.x;         // 128
    const float* WuL = Wu + (size_t)l * 2 * HH * HH;   // [256][128]
    if (r < HH) {
        g_Ws[((size_t)l * 256 + r) * HH + j] = __float2half(WuL[(size_t)r * HH + j]);
    } else if (r < 2 * HH) {
        int rr = r - HH;
        __shared__ float wm[HH];
        wm[j] = Wm[((size_t)l * HH + rr) * HH + j];
        __syncthreads();
        float acc = 0.f;
#pragma unroll 8
        for (int k = 0; k < HH; k++)
            acc += wm[k] * WuL[(size_t)(HH + k) * HH + j];
        g_Ws[((size_t)l * 256 + r) * HH + j] = __float2half(acc);
    } else {
        __shared__ float bb[HH];
        bb[j] = bm[l * HH + j];
        __syncthreads();
        float acc = bu[l * HH + j];
#pragma unroll 8
        for (int k = 0; k < HH; k++)
            acc += bb[k] * WuL[(size_t)(HH + k) * HH + j];
        g_bc[l * HH + j] = acc;
    }
}

// ---------------- comb[:,0:128] = h0_16 ----------------
__global__ void copy_h0()
{
    int i = blockIdx.x * 256 + threadIdx.x;
    if (i < NN * HH / 8) {
        int n = i >> 4;
        int c = (i & 15) * 8;
        *reinterpret_cast<float4*>(g_comb + (size_t)n * 256 + c) =
            *reinterpret_cast<const float4*>(g_h016 + (size_t)n * 128 + c);
    }
}

// ---------------- fp16 wmma GEMM (small K: projections/updates) ----------------
__global__ __launch_bounds__(256) void gemm_k(
    const __half* __restrict__ A, int lda,
    const __half* __restrict__ B, int ldb,
    float* __restrict__ C32, int ldc32,
    __half* __restrict__ C16, int ldc16,
    const float* __restrict__ bias,
    const float* __restrict__ rowscale,
    int K, int relu)
{
    constexpr int BM = 64, BN = 128, BK = 64;
    __shared__ __align__(16) char sraw[33792];
    __half (*sA)[BK + 8] = reinterpret_cast<__half(*)[BK + 8]>(sraw);
    __half (*sB)[BN + 8] = reinterpret_cast<__half(*)[BN + 8]>(sraw + 9216);
    float* sC = reinterpret_cast<float*>(sraw);

    int tid = threadIdx.x;
    int wid = tid >> 5;
    int bm = blockIdx.x * BM;
    int wm = (wid >> 2) * 32;
    int wn = (wid & 3) * 32;

    wmma::fragment<wmma::accumulator, 16, 16, 16, float> acc[2][2];
#pragma unroll
    for (int i = 0; i < 2; i++)
#pragma unroll
        for (int j = 0; j < 2; j++)
            wmma::fill_fragment(acc[i][j], 0.0f);

    float4 ra[2], rb[4];
#pragma unroll
    for (int i = 0; i < 2; i++) {
        int idx = tid * 8 + i * 2048;
        ra[i] = *reinterpret_cast<const float4*>(A + (size_t)(bm + (idx >> 6)) * lda + (idx & 63));
    }
#pragma unroll
    for (int i = 0; i < 4; i++) {
        int idx = tid * 8 + i * 2048;
        rb[i] = *reinterpret_cast<const float4*>(B + (size_t)(idx >> 7) * ldb + (idx & 127));
    }

    int nk = K >> 6;
    for (int kt = 0; kt < nk; kt++) {
#pragma unroll
        for (int i = 0; i < 2; i++) {
            int idx = tid * 8 + i * 2048;
            *reinterpret_cast<float4*>(&sA[idx >> 6][idx & 63]) = ra[i];
        }
#pragma unroll
        for (int i = 0; i < 4; i++) {
            int idx = tid * 8 + i * 2048;
            *reinterpret_cast<float4*>(&sB[idx >> 7][idx & 127]) = rb[i];
        }
        __syncthreads();

        if (kt + 1 < nk) {
            int k0 = (kt + 1) << 6;
#pragma unroll
            for (int i = 0; i < 2; i++) {
                int idx = tid * 8 + i * 2048;
                ra[i] = *reinterpret_cast<const float4*>(A + (size_t)(bm + (idx >> 6)) * lda + k0 + (idx & 63));
            }
#pragma unroll
            for (int i = 0; i < 4; i++) {
                int idx = tid * 8 + i * 2048;
                rb[i] = *reinterpret_cast<const float4*>(B + (size_t)(k0 + (idx >> 7)) * ldb + (idx & 127));
            }
        }

#pragma unroll
        for (int kk = 0; kk < BK; kk += 16) {
            wmma::fragment<wmma::matrix_a, 16, 16, 16, __half, wmma::row_major> fa[2];
            wmma::fragment<wmma::matrix_b, 16, 16, 16, __half, wmma::row_major> fb[2];
            wmma::load_matrix_sync(fa[0], &sA[wm][kk], BK + 8);
            wmma::load_matrix_sync(fa[1], &sA[wm + 16][kk], BK + 8);
            wmma::load_matrix_sync(fb[0], &sB[kk][wn], BN + 8);
            wmma::load_matrix_sync(fb[1], &sB[kk][wn + 16], BN + 8);
#pragma unroll
            for (int i = 0; i < 2; i++)
#pragma unroll
                for (int j = 0; j < 2; j++)
                    wmma::mma_sync(acc[i][j], fa[i], fb[j], acc[i][j]);
        }
        __syncthreads();
    }

#pragma unroll
    for (int i = 0; i < 2; i++)
#pragma unroll
        for (int j = 0; j < 2; j++)
            wmma::store_matrix_sync(sC + (size_t)(wm + 16 * i) * 132 + (wn + 16 * j),
                                    acc[i][j], 132, wmma::mem_row_major);
    __syncthreads();

    for (int e = tid; e < BM * BN; e += 256) {
        int r = e >> 7, c = e & 127;
        float vv = sC[r * 132 + c];
        if (rowscale) vv *= rowscale[bm + r];
        if (bias) vv += bias[c];
        if (relu) vv = fmaxf(vv, 0.0f);
        if (C16) C16[(size_t)(bm + r) * ldc16 + c] = __float2half(vv);
        if (C32) C32[(size_t)(bm + r) * ldc32 + c] = vv;
    }
}

// ---------------- attention over layers + output projection ----------------
__global__ __launch_bounds__(256) void attn_out(
    const float* __restrict__ Wa, const float* __restrict__ ba,
    const float* __restrict__ v, const float* __restrict__ Wo,
    const float* __restrict__ bo, float* __restrict__ out)
{
    __shared__ float sWa[HH * 4];
    __shared__ float sba[4], sv[4];
    __shared__ float smix[8][4][132];
    int t = threadIdx.x;
    for (int i = t; i < HH * 4; i += 256) sWa[i] = Wa[i];
    if (t < 4) { sba[t] = ba[t]; sv[t] = v[t]; }
    __syncthreads();

    int w = t >> 5, lane = t & 31;
    for (int q = 0; q < 4; q++) {
        int n = blockIdx.x * 32 + w * 4 + q;
        float e[3][4];
#pragma unroll
        for (int l = 0; l < 3; l++)
#pragma unroll
            for (int ii = 0; ii < 4; ii++)
                e[l][ii] = g_embs[((size_t)l * NN + n) * HH + lane + 32 * ii];

        float sc[3];
#pragma unroll
        for (int l = 0; l < 3; l++) {
            float s = 0.f;
#pragma unroll
            for (int hd = 0; hd < 4; hd++) {
                float d = 0.f;
#pragma unroll
                for (int ii = 0; ii < 4; ii++)
                    d += e[l][ii] * sWa[(lane + 32 * ii) * 4 + hd];
#pragma unroll
                for (int o = 16; o; o >>= 1) d += __shfl_xor_sync(0xFFFFFFFFu, d, o);
                s += tanhf(d + sba[hd]) * sv[hd];
            }
            sc[l] = s;
        }
        float mx = fmaxf(sc[0], fmaxf(sc[1], sc[2]));
        float w0 = expf(sc[0] - mx), w1 = expf(sc[1] - mx), w2 = expf(sc[2] - mx);
        float inv = 1.0f / (w0 + w1 + w2);
        w0 *= inv; w1 *= inv; w2 *= inv;
#pragma unroll
        for (int ii = 0; ii < 4; ii++)
            smix[w][q][lane + 32 * ii] = w0 * e[0][ii] + w1 * e[1][ii] + w2 * e[2][ii];
        __syncwarp();
#pragma unroll
        for (int jj = 0; jj < 4; jj++) {
            int j = lane + 32 * jj;
            float a = bo[j];
            for (int h = 0; h < HH; h++)
                a += smix[w][q][h] * Wo[h * HH + j];
            out[(size_t)n * HH + j] = a;
        }
        __syncwarp();
    }
}

// ---------------- deterministic mean reduction ----------------
__global__ void mean_part(const float* __restrict__ out)
{
    int b = blockIdx.x;
    int t = threadIdx.x;
    float s = 0.f;
    for (int r = 0; r < 64; r++)
        s += out[((size_t)b * 64 + r) * HH + t];
    g_part[b * HH + t] = s;
}
__global__ void mean_fin(float* __restrict__ gout)
{
    int t = threadIdx.x;
    float s = 0.f;
    for (int i = 0; i < 128; i++) s += g_part[i * HH + t];
    gout[t] = s * (1.0f / (float)NN);
}

// ---------------- launcher ----------------
extern "C" void kernel_launch(void* const* d_in, const int* in_sizes, int n_in,
                              void* d_out, int out_size)
{
    (void)in_sizes; (void)n_in; (void)out_size;
    const float* nf  = (const float*)d_in[0];
    const float* adj = (const float*)d_in[1];
    const float* bi  = (const float*)d_in[3];
    const float* Wa  = (const float*)d_in[8];
    const float* ba  = (const float*)d_in[9];
    const float* v   = (const float*)d_in[10];
    const float* Wo  = (const float*)d_in[11];
    const float* bo  = (const float*)d_in[12];
    float* out = (float*)d_out;

    __half *A16, *X16, *Wi16, *Ws, *h016, *comb;
    float *invdeg, *embs, *ps, *bc;
    cudaGetSymbolAddress((void**)&A16,   g_A16);
    cudaGetSymbolAddress((void**)&X16,   g_X16);
    cudaGetSymbolAddress((void**)&Wi16,  g_Wi16);
    cudaGetSymbolAddress((void**)&Ws,    g_Ws);
    cudaGetSymbolAddress((void**)&h016,  g_h016);
    cudaGetSymbolAddress((void**)&comb,  g_comb);
    cudaGetSymbolAddress((void**)&invdeg, g_invdeg);
    cudaGetSymbolAddress((void**)&embs,   g_embs);
    cudaGetSymbolAddress((void**)&ps,     g_ps);
    cudaGetSymbolAddress((void**)&bc,     g_bc);

    cudaFuncSetAttribute(gemm_big, cudaFuncAttributeMaxDynamicSharedMemorySize, GB_SMEM);

    // 1. adj -> fp16 + invdeg (one pass over 805MB)
    prep_adj<<<NNET * NN, 256>>>(adj);

    // 2. fp16 conversions + fused-weight precompute
    f2h<<<(NN * IND / 4 + 255) / 256, 256>>>(nf, X16, NN * IND / 4);
    f2h<<<(IND * HH / 4 + 255) / 256, 256>>>((const float*)d_in[2], Wi16, IND * HH / 4);
    fuse_w<<<dim3(2 * HH + 1, NL), HH>>>((const float*)d_in[4], (const float*)d_in[6],
                                          (const float*)d_in[5], (const float*)d_in[7]);

    // 3. h0 = X @ Wi + bi  (fp16 out)
    gemm_k<<<128, 256>>>(X16, IND, Wi16, HH,
                         nullptr, 0, h016, HH, bi, nullptr, IND, 0);

    // 4. message passing (pipelined HMMA SpMM, split-K=4, fused update)
    for (int net = 0; net < NNET; net++) {
        copy_h0<<<(NN * HH / 8 + 255) / 256, 256>>>();
        for (int l = 0; l < NL; l++) {
            const __half* Bsrc = (l == 0) ? h016 : comb;
            int ldb = (l == 0) ? HH : 2 * HH;
            // partials = A[net] @ h  (fp32, four K-quarters, 256 CTAs)
            gemm_big<<<dim3(NN / 128, 4), 256, GB_SMEM>>>(
                A16 + (size_t)net * NN * NN, Bsrc, ldb, ps);
            // comb[:,128:256] = (p0+p1+p2+p3) * invdeg  (fp16)
            combine_k<<<NN * HH / 4 / 256, 256>>>(invdeg + net * NN);
            // h = relu([h|msg] @ Ws[l] + bc[l]) -> comb[:,0:128] (+fp32 embs if last)
            float* c32 = (l == NL - 1) ? (embs + (size_t)net * NN * HH) : nullptr;
            gemm_k<<<128, 256>>>(comb, 2 * HH, Ws + (size_t)l * 2 * HH * HH, HH,
                                 c32, HH, comb, 2 * HH,
                                 bc + l * HH, nullptr, 2 * HH, 1);
        }
    }

    // 5. cross-layer attention + output projection
    attn_out<<<NN / 32, 256>>>(Wa, ba, v, Wo, bo, out);

    // 6. deterministic mean over nodes
    mean_part<<<128, 128>>>(out);
    mean_fin<<<1, 128>>>(out + (size_t)NN * HH);
}

// round 8
// speedup vs baseline: 1.0192x; 1.0192x over previous
#include <cuda_runtime.h>
#include <cuda_fp16.h>
#include <mma.h>
#include <cstdint>
#include <cstddef>

using namespace nvcuda;

#define NN    8192
#define IND   256
#define HH    128
#define NL    3
#define NNET  3

// ---------------- device scratch (static, allowed) ----------------
__device__ __align__(16) __half g_A16[(size_t)NN * NN];          // one net's fp16 adj (134 MB)
__device__ __align__(16) __half g_X16[NN * IND];
__device__ __align__(16) __half g_Wi16[IND * HH];
__device__ __align__(16) __half g_Ws[NL * 2 * HH * HH];          // fused [Wu_top; Wm@Wu_bot]
__device__ float g_bc[NL * HH];                                   // fused bias
__device__ __align__(16) __half g_h016[NN * HH];
__device__ __align__(16) __half g_comb[NN * 2 * HH];             // [h | msg]
__device__ __align__(16) float g_ps[2 * NN * HH];                // split-K fp32 partials
__device__ float g_degp[2 * NN];                                  // split-K degree partials
__device__ float g_invdeg[NN];                                    // current net's 1/deg
__device__ float g_embs[(size_t)NNET * NN * HH];                 // per-net final layer embeddings
__device__ float g_part[128 * HH];

// ---------------- helpers ----------------
__device__ __forceinline__ uint32_t s2u(const void* p){
    uint32_t a;
    asm("{ .reg .u64 t; cvta.to.shared.u64 t, %1; cvt.u32.u64 %0, t; }" : "=r"(a) : "l"(p));
    return a;
}
__device__ __forceinline__ void cp16(uint32_t dst, const void* src){
    asm volatile("cp.async.cg.shared.global [%0], [%1], 16;" :: "r"(dst), "l"(src));
}
#define CP_COMMIT() asm volatile("cp.async.commit_group;" ::: "memory")
#define CP_WAIT2()  asm volatile("cp.async.wait_group 2;" ::: "memory")
#define CP_WAIT1()  asm volatile("cp.async.wait_group 1;" ::: "memory")

// =================== round-4 pipelined SpMM (layers 1-2): part = A16 @ B ===================
// grid (64, 2): blockIdx.x = M tile (128 rows), blockIdx.y = K half (4096).
// 4-stage cp.async pipeline, BK=64, 8 warps each computing 32x64.
#define GB_S    4
#define GB_ASZ  (128 * 72 * 2)                  // 18432 B
#define GB_BSZ  (64 * 136 * 2)                  // 17408 B
#define GB_STG  (GB_ASZ + GB_BSZ)               // 35840 B
#define GB_SMEM (GB_S * GB_STG)                 // 143360 B

__global__ __launch_bounds__(256, 1) void gemm_big(
    const __half* __restrict__ A,
    const __half* __restrict__ B, int ldb,
    float* __restrict__ part)
{
    extern __shared__ char dsm[];
    uint32_t sb = s2u(dsm);
    int tid = threadIdx.x;
    int wid = tid >> 5;
    int bm = blockIdx.x * 128;
    int kbase = blockIdx.y * 4096;
    int wm = (wid >> 1) * 32;
    int wn = (wid & 1) * 64;

    auto load_stage = [&](int st, int kt) {
        int k0 = kbase + kt * 64;
        uint32_t abase = sb + st * GB_STG;
        uint32_t bbase = abase + GB_ASZ;
#pragma unroll
        for (int i = 0; i < 4; i++) {
            int idx = tid + i * 256;
            int r = idx >> 3, c = idx & 7;
            cp16(abase + r * 144 + c * 16,
                 A + (size_t)(bm + r) * NN + k0 + c * 8);
        }
#pragma unroll
        for (int i = 0; i < 4; i++) {
            int idx = tid + i * 256;
            int r = idx >> 4, c = idx & 15;
            cp16(bbase + r * 272 + c * 16,
                 B + (size_t)(k0 + r) * ldb + c * 8);
        }
    };

    wmma::fragment<wmma::accumulator, 16, 16, 16, float> acc[2][4];
#pragma unroll
    for (int i = 0; i < 2; i++)
#pragma unroll
        for (int j = 0; j < 4; j++)
            wmma::fill_fragment(acc[i][j], 0.0f);

#pragma unroll
    for (int s = 0; s < GB_S - 1; s++) { load_stage(s, s); CP_COMMIT(); }

    const int nk = 4096 / 64;
    for (int kt = 0; kt < nk; kt++) {
        CP_WAIT2();
        __syncthreads();
        if (kt + GB_S - 1 < nk) load_stage((kt + GB_S - 1) & (GB_S - 1), kt + GB_S - 1);
        CP_COMMIT();

        int st = kt & (GB_S - 1);
        const __half* pA = reinterpret_cast<const __half*>(dsm + st * GB_STG);
        const __half* pB = reinterpret_cast<const __half*>(dsm + st * GB_STG + GB_ASZ);
#pragma unroll
        for (int kk = 0; kk < 64; kk += 16) {
            wmma::fragment<wmma::matrix_a, 16, 16, 16, __half, wmma::row_major> fa[2];
            wmma::fragment<wmma::matrix_b, 16, 16, 16, __half, wmma::row_major> fb[4];
#pragma unroll
            for (int i = 0; i < 2; i++)
                wmma::load_matrix_sync(fa[i], pA + (size_t)(wm + 16 * i) * 72 + kk, 72);
#pragma unroll
            for (int j = 0; j < 4; j++)
                wmma::load_matrix_sync(fb[j], pB + (size_t)kk * 136 + wn + 16 * j, 136);
#pragma unroll
            for (int i = 0; i < 2; i++)
#pragma unroll
                for (int j = 0; j < 4; j++)
                    wmma::mma_sync(acc[i][j], fa[i], fb[j], acc[i][j]);
        }
        __syncthreads();
    }

    float* sC = reinterpret_cast<float*>(dsm);     // 128 x 132
#pragma unroll
    for (int i = 0; i < 2; i++)
#pragma unroll
        for (int j = 0; j < 4; j++)
            wmma::store_matrix_sync(sC + (size_t)(wm + 16 * i) * 132 + wn + 16 * j,
                                    acc[i][j], 132, wmma::mem_row_major);
    __syncthreads();

    float* out = part + (size_t)blockIdx.y * NN * HH + (size_t)bm * HH;
    for (int e = tid; e < 128 * 128 / 4; e += 256) {
        int r = e >> 5, c = (e & 31) * 4;
        *reinterpret_cast<float4*>(out + (size_t)r * HH + c) =
            *reinterpret_cast<const float4*>(sC + (size_t)r * 132 + c);
    }
}

// ====== fused layer-0 SpMM: reads fp32 adj, converts->fp16 (emit g_A16), rowsums, MMA ======
// grid (64, 2). 3-stage pipeline: A fp32 staging -> convert to fp16 smem -> HMMA.
#define GC_S     3
#define GC_A32   (128 * 68 * 4)                 // 34816 B (pad 68 floats)
#define GC_A16   (128 * 72 * 2)                 // 18432 B
#define GC_B16   (64 * 136 * 2)                 // 17408 B
#define GC_STG   (GC_A32 + GC_A16 + GC_B16)     // 70656 B
#define GC_SMEM  (GC_S * GC_STG)                // 211968 B

__global__ __launch_bounds__(256, 1) void gemm_cvt(
    const float* __restrict__ A32,              // raw adj for this net [NN x NN] fp32
    const __half* __restrict__ B, int ldb,
    float* __restrict__ part)
{
    extern __shared__ char dsm[];
    uint32_t sb = s2u(dsm);
    int tid = threadIdx.x;
    int wid = tid >> 5;
    int bm = blockIdx.x * 128;
    int kbase = blockIdx.y * 4096;
    int wm = (wid >> 1) * 32;
    int wn = (wid & 1) * 64;

    auto load_stage = [&](int st, int kt) {
        int k0 = kbase + kt * 64;
        uint32_t a32b = sb + st * GC_STG;
        uint32_t b16b = a32b + GC_A32 + GC_A16;
#pragma unroll
        for (int i = 0; i < 8; i++) {           // A fp32: 128 rows x 64 floats
            int idx = tid + i * 256;
            int r = idx >> 4, c = idx & 15;     // c: 16B = 4 floats
            cp16(a32b + r * 272 + c * 16,
                 A32 + (size_t)(bm + r) * NN + k0 + c * 4);
        }
#pragma unroll
        for (int i = 0; i < 4; i++) {           // B fp16: 64 rows x 128 halves
            int idx = tid + i * 256;
            int r = idx >> 4, c = idx & 15;
            cp16(b16b + r * 272 + c * 16,
                 B + (size_t)(k0 + r) * ldb + c * 8);
        }
    };

    wmma::fragment<wmma::accumulator, 16, 16, 16, float> acc[2][4];
#pragma unroll
    for (int i = 0; i < 2; i++)
#pragma unroll
        for (int j = 0; j < 4; j++)
            wmma::fill_fragment(acc[i][j], 0.0f);

    load_stage(0, 0); CP_COMMIT();
    load_stage(1, 1); CP_COMMIT();

    // per-thread convert coords: row r = tid/2, 32-float half cs
    int crow = tid >> 1;
    int ccol = (tid & 1) * 32;
    float rsum = 0.f;

    const int nk = 4096 / 64;
    int st_use = 0, st_load = 2;
    for (int kt = 0; kt < nk; kt++) {
        CP_WAIT1();
        __syncthreads();
        if (kt + 2 < nk) load_stage(st_load, kt + 2);
        CP_COMMIT();

        char* stg = dsm + st_use * GC_STG;
        const float* pA32 = reinterpret_cast<const float*>(stg);         // ld 68
        __half* pA16 = reinterpret_cast<__half*>(stg + GC_A32);          // ld 72
        const __half* pB = reinterpret_cast<const __half*>(stg + GC_A32 + GC_A16);

        // ---- convert my 32 floats: fp32 smem -> fp16 smem + STG to g_A16 + rowsum ----
        {
            int k0 = kbase + kt * 64;
            float lsum = 0.f;
#pragma unroll
            for (int j = 0; j < 4; j++) {
                float4 f0 = *reinterpret_cast<const float4*>(pA32 + (size_t)crow * 68 + ccol + j * 8);
                float4 f1 = *reinterpret_cast<const float4*>(pA32 + (size_t)crow * 68 + ccol + j * 8 + 4);
                lsum += ((f0.x + f0.y) + (f0.z + f0.w)) + ((f1.x + f1.y) + (f1.z + f1.w));
                __half2 h0 = __floats2half2_rn(f0.x, f0.y);
                __half2 h1 = __floats2half2_rn(f0.z, f0.w);
                __half2 h2 = __floats2half2_rn(f1.x, f1.y);
                __half2 h3 = __floats2half2_rn(f1.z, f1.w);
                uint4 u;
                u.x = *reinterpret_cast<unsigned*>(&h0);
                u.y = *reinterpret_cast<unsigned*>(&h1);
                u.z = *reinterpret_cast<unsigned*>(&h2);
                u.w = *reinterpret_cast<unsigned*>(&h3);
                // 8 halves = 16B to smem fp16 tile and to global A16 cache
                *reinterpret_cast<uint4*>(pA16 + (size_t)crow * 72 + ccol + j * 8) = u;
                *reinterpret_cast<uint4*>(g_A16 + (size_t)(bm + crow) * NN + k0 + ccol + j * 8) = u;
            }
            float other = __shfl_xor_sync(0xFFFFFFFFu, lsum, 1);
            if ((tid & 1) == 0) rsum += lsum + other;
        }
        __syncthreads();

        // ---- HMMA on converted tile ----
#pragma unroll
        for (int kk = 0; kk < 64; kk += 16) {
            wmma::fragment<wmma::matrix_a, 16, 16, 16, __half, wmma::row_major> fa[2];
            wmma::fragment<wmma::matrix_b, 16, 16, 16, __half, wmma::row_major> fb[4];
#pragma unroll
            for (int i = 0; i < 2; i++)
                wmma::load_matrix_sync(fa[i], pA16 + (size_t)(wm + 16 * i) * 72 + kk, 72);
#pragma unroll
            for (int j = 0; j < 4; j++)
                wmma::load_matrix_sync(fb[j], pB + (size_t)kk * 136 + wn + 16 * j, 136);
#pragma unroll
            for (int i = 0; i < 2; i++)
#pragma unroll
                for (int j = 0; j < 4; j++)
                    wmma::mma_sync(acc[i][j], fa[i], fb[j], acc[i][j]);
        }
        __syncthreads();
        st_use = (st_use + 1) % GC_S;
        st_load = (st_load + 1) % GC_S;
    }

    // degree partials (one writer per row)
    if ((tid & 1) == 0)
        g_degp[(size_t)blockIdx.y * NN + bm + crow] = rsum;

    // epilogue
    float* sC = reinterpret_cast<float*>(dsm);     // 128 x 132
#pragma unroll
    for (int i = 0; i < 2; i++)
#pragma unroll
        for (int j = 0; j < 4; j++)
            wmma::store_matrix_sync(sC + (size_t)(wm + 16 * i) * 132 + wn + 16 * j,
                                    acc[i][j], 132, wmma::mem_row_major);
    __syncthreads();

    float* out = part + (size_t)blockIdx.y * NN * HH + (size_t)bm * HH;
    for (int e = tid; e < 128 * 128 / 4; e += 256) {
        int r = e >> 5, c = (e & 31) * 4;
        *reinterpret_cast<float4*>(out + (size_t)r * HH + c) =
            *reinterpret_cast<const float4*>(sC + (size_t)r * 132 + c);
    }
}

// ---- layer-0 combine: inv = 1/max(deg,1); comb[:,128:256] = (p0+p1)*inv; store invdeg ----
__global__ void combine0()
{
    int i = blockIdx.x * 256 + threadIdx.x;       // float4 group
    int n = i >> 5, coff = (i & 31) * 4;
    float d = g_degp[n] + g_degp[NN + n];
    float s = 1.0f / fmaxf(d, 1.0f);
    if ((i & 31) == 0) g_invdeg[n] = s;
    const float4* p = reinterpret_cast<const float4*>(g_ps);
    float4 a = p[i], b = p[i + NN * HH / 4];
    __half2 h0 = __floats2half2_rn((a.x + b.x) * s, (a.y + b.y) * s);
    __half2 h1 = __floats2half2_rn((a.z + b.z) * s, (a.w + b.w) * s);
    uint2 u;
    u.x = *reinterpret_cast<unsigned*>(&h0);
    u.y = *reinterpret_cast<unsigned*>(&h1);
    *reinterpret_cast<uint2*>(g_comb + (size_t)n * 256 + 128 + coff) = u;
}

// ---- layers 1-2 combine: comb[:,128:256] = (p0+p1)*invdeg ----
__global__ void combine_k()
{
    int i = blockIdx.x * 256 + threadIdx.x;
    int n = i >> 5, coff = (i & 31) * 4;
    float s = g_invdeg[n];
    const float4* p = reinterpret_cast<const float4*>(g_ps);
    float4 a = p[i], b = p[i + NN * HH / 4];
    __half2 h0 = __floats2half2_rn((a.x + b.x) * s, (a.y + b.y) * s);
    __half2 h1 = __floats2half2_rn((a.z + b.z) * s, (a.w + b.w) * s);
    uint2 u;
    u.x = *reinterpret_cast<unsigned*>(&h0);
    u.y = *reinterpret_cast<unsigned*>(&h1);
    *reinterpret_cast<uint2*>(g_comb + (size_t)n * 256 + 128 + coff) = u;
}

// ---------------- generic fp32 -> fp16 convert ----------------
__global__ void f2h(const float* __restrict__ src, __half* __restrict__ dst, int n4)
{
    int i = blockIdx.x * blockDim.x + threadIdx.x;
    if (i < n4) {
        float4 f = reinterpret_cast<const float4*>(src)[i];
        __half2 a = __floats2half2_rn(f.x, f.y);
        __half2 b = __floats2half2_rn(f.z, f.w);
        uint2 u;
        u.x = *reinterpret_cast<unsigned*>(&a);
        u.y = *reinterpret_cast<unsigned*>(&b);
        *reinterpret_cast<uint2*>(dst + (size_t)i * 4) = u;
    }
}

// ------- fused weight precompute: Ws[l] = [Wu_top ; Wm[l]@Wu_bot], bc[l] = bm@Wu_bot + bu -------
__global__ void fuse_w(const float* __restrict__ Wm, const float* __restrict__ Wu,
                       const float* __restrict__ bm, const float* __restrict__ bu)
{
    int l = blockIdx.y;
    int r = blockIdx.x;          // 0..256
    int j = threadIdx.x;         // 128
    const float* WuL = Wu + (size_t)l * 2 * HH * HH;   // [256][128]
    if (r < HH) {
        g_Ws[((size_t)l * 256 + r) * HH + j] = __float2half(WuL[(size_t)r * HH + j]);
    } else if (r < 2 * HH) {
        int rr = r - HH;
        __shared__ float wm[HH];
        wm[j] = Wm[((size_t)l * HH + rr) * HH + j];
        __syncthreads();
        float acc = 0.f;
#pragma unroll 8
        for (int k = 0; k < HH; k++)
            acc += wm[k] * WuL[(size_t)(HH + k) * HH + j];
        g_Ws[((size_t)l * 256 + r) * HH + j] = __float2half(acc);
    } else {
        __shared__ float bb[HH];
        bb[j] = bm[l * HH + j];
        __syncthreads();
        float acc = bu[l * HH + j];
#pragma unroll 8
        for (int k = 0; k < HH; k++)
            acc += bb[k] * WuL[(size_t)(HH + k) * HH + j];
        g_bc[l * HH + j] = acc;
    }
}

// ---------------- comb[:,0:128] = h0_16 ----------------
__global__ void copy_h0()
{
    int i = blockIdx.x * 256 + threadIdx.x;
    if (i < NN * HH / 8) {
        int n = i >> 4;
        int c = (i & 15) * 8;
        *reinterpret_cast<float4*>(g_comb + (size_t)n * 256 + c) =
            *reinterpret_cast<const float4*>(g_h016 + (size_t)n * 128 + c);
    }
}

// ---------------- fp16 wmma GEMM (small K: projections/updates) ----------------
__global__ __launch_bounds__(256) void gemm_k(
    const __half* __restrict__ A, int lda,
    const __half* __restrict__ B, int ldb,
    float* __restrict__ C32, int ldc32,
    __half* __restrict__ C16, int ldc16,
    const float* __restrict__ bias,
    const float* __restrict__ rowscale,
    int K, int relu)
{
    constexpr int BM = 64, BN = 128, BK = 64;
    __shared__ __align__(16) char sraw[33792];
    __half (*sA)[BK + 8] = reinterpret_cast<__half(*)[BK + 8]>(sraw);
    __half (*sB)[BN + 8] = reinterpret_cast<__half(*)[BN + 8]>(sraw + 9216);
    float* sC = reinterpret_cast<float*>(sraw);

    int tid = threadIdx.x;
    int wid = tid >> 5;
    int bm = blockIdx.x * BM;
    int wm = (wid >> 2) * 32;
    int wn = (wid & 3) * 32;

    wmma::fragment<wmma::accumulator, 16, 16, 16, float> acc[2][2];
#pragma unroll
    for (int i = 0; i < 2; i++)
#pragma unroll
        for (int j = 0; j < 2; j++)
            wmma::fill_fragment(acc[i][j], 0.0f);

    float4 ra[2], rb[4];
#pragma unroll
    for (int i = 0; i < 2; i++) {
        int idx = tid * 8 + i * 2048;
        ra[i] = *reinterpret_cast<const float4*>(A + (size_t)(bm + (idx >> 6)) * lda + (idx & 63));
    }
#pragma unroll
    for (int i = 0; i < 4; i++) {
        int idx = tid * 8 + i * 2048;
        rb[i] = *reinterpret_cast<const float4*>(B + (size_t)(idx >> 7) * ldb + (idx & 127));
    }

    int nk = K >> 6;
    for (int kt = 0; kt < nk; kt++) {
#pragma unroll
        for (int i = 0; i < 2; i++) {
            int idx = tid * 8 + i * 2048;
            *reinterpret_cast<float4*>(&sA[idx >> 6][idx & 63]) = ra[i];
        }
#pragma unroll
        for (int i = 0; i < 4; i++) {
            int idx = tid * 8 + i * 2048;
            *reinterpret_cast<float4*>(&sB[idx >> 7][idx & 127]) = rb[i];
        }
        __syncthreads();

        if (kt + 1 < nk) {
            int k0 = (kt + 1) << 6;
#pragma unroll
            for (int i = 0; i < 2; i++) {
                int idx = tid * 8 + i * 2048;
                ra[i] = *reinterpret_cast<const float4*>(A + (size_t)(bm + (idx >> 6)) * lda + k0 + (idx & 63));
            }
#pragma unroll
            for (int i = 0; i < 4; i++) {
                int idx = tid * 8 + i * 2048;
                rb[i] = *reinterpret_cast<const float4*>(B + (size_t)(k0 + (idx >> 7)) * ldb + (idx & 127));
            }
        }

#pragma unroll
        for (int kk = 0; kk < BK; kk += 16) {
            wmma::fragment<wmma::matrix_a, 16, 16, 16, __half, wmma::row_major> fa[2];
            wmma::fragment<wmma::matrix_b, 16, 16, 16, __half, wmma::row_major> fb[2];
            wmma::load_matrix_sync(fa[0], &sA[wm][kk], BK + 8);
            wmma::load_matrix_sync(fa[1], &sA[wm + 16][kk], BK + 8);
            wmma::load_matrix_sync(fb[0], &sB[kk][wn], BN + 8);
            wmma::load_matrix_sync(fb[1], &sB[kk][wn + 16], BN + 8);
#pragma unroll
            for (int i = 0; i < 2; i++)
#pragma unroll
                for (int j = 0; j < 2; j++)
                    wmma::mma_sync(acc[i][j], fa[i], fb[j], acc[i][j]);
        }
        __syncthreads();
    }

#pragma unroll
    for (int i = 0; i < 2; i++)
#pragma unroll
        for (int j = 0; j < 2; j++)
            wmma::store_matrix_sync(sC + (size_t)(wm + 16 * i) * 132 + (wn + 16 * j),
                                    acc[i][j], 132, wmma::mem_row_major);
    __syncthreads();

    for (int e = tid; e < BM * BN; e += 256) {
        int r = e >> 7, c = e & 127;
        float vv = sC[r * 132 + c];
        if (rowscale) vv *= rowscale[bm + r];
        if (bias) vv += bias[c];
        if (relu) vv = fmaxf(vv, 0.0f);
        if (C16) C16[(size_t)(bm + r) * ldc16 + c] = __float2half(vv);
        if (C32) C32[(size_t)(bm + r) * ldc32 + c] = vv;
    }
}

// ---------------- attention over layers + output projection ----------------
__global__ __launch_bounds__(256) void attn_out(
    const float* __restrict__ Wa, const float* __restrict__ ba,
    const float* __restrict__ v, const float* __restrict__ Wo,
    const float* __restrict__ bo, float* __restrict__ out)
{
    __shared__ float sWa[HH * 4];
    __shared__ float sba[4], sv[4];
    __shared__ float smix[8][4][132];
    int t = threadIdx.x;
    for (int i = t; i < HH * 4; i += 256) sWa[i] = Wa[i];
    if (t < 4) { sba[t] = ba[t]; sv[t] = v[t]; }
    __syncthreads();

    int w = t >> 5, lane = t & 31;
    for (int q = 0; q < 4; q++) {
        int n = blockIdx.x * 32 + w * 4 + q;
        float e[3][4];
#pragma unroll
        for (int l = 0; l < 3; l++)
#pragma unroll
            for (int ii = 0; ii < 4; ii++)
                e[l][ii] = g_embs[((size_t)l * NN + n) * HH + lane + 32 * ii];

        float sc[3];
#pragma unroll
        for (int l = 0; l < 3; l++) {
            float s = 0.f;
#pragma unroll
            for (int hd = 0; hd < 4; hd++) {
                float d = 0.f;
#pragma unroll
                for (int ii = 0; ii < 4; ii++)
                    d += e[l][ii] * sWa[(lane + 32 * ii) * 4 + hd];
#pragma unroll
                for (int o = 16; o; o >>= 1) d += __shfl_xor_sync(0xFFFFFFFFu, d, o);
                s += tanhf(d + sba[hd]) * sv[hd];
            }
            sc[l] = s;
        }
        float mx = fmaxf(sc[0], fmaxf(sc[1], sc[2]));
        float w0 = expf(sc[0] - mx), w1 = expf(sc[1] - mx), w2 = expf(sc[2] - mx);
        float inv = 1.0f / (w0 + w1 + w2);
        w0 *= inv; w1 *= inv; w2 *= inv;
#pragma unroll
        for (int ii = 0; ii < 4; ii++)
            smix[w][q][lane + 32 * ii] = w0 * e[0][ii] + w1 * e[1][ii] + w2 * e[2][ii];
        __syncwarp();
#pragma unroll
        for (int jj = 0; jj < 4; jj++) {
            int j = lane + 32 * jj;
            float a = bo[j];
            for (int h = 0; h < HH; h++)
                a += smix[w][q][h] * Wo[h * HH + j];
            out[(size_t)n * HH + j] = a;
        }
        __syncwarp();
    }
}

// ---------------- deterministic mean reduction ----------------
__global__ void mean_part(const float* __restrict__ out)
{
    int b = blockIdx.x;
    int t = threadIdx.x;
    float s = 0.f;
    for (int r = 0; r < 64; r++)
        s += out[((size_t)b * 64 + r) * HH + t];
    g_part[b * HH + t] = s;
}
__global__ void mean_fin(float* __restrict__ gout)
{
    int t = threadIdx.x;
    float s = 0.f;
    for (int i = 0; i < 128; i++) s += g_part[i * HH + t];
    gout[t] = s * (1.0f / (float)NN);
}

// ---------------- launcher ----------------
extern "C" void kernel_launch(void* const* d_in, const int* in_sizes, int n_in,
                              void* d_out, int out_size)
{
    (void)in_sizes; (void)n_in; (void)out_size;
    const float* nf  = (const float*)d_in[0];
    const float* adj = (const float*)d_in[1];
    const float* bi  = (const float*)d_in[3];
    const float* Wa  = (const float*)d_in[8];
    const float* ba  = (const float*)d_in[9];
    const float* v   = (const float*)d_in[10];
    const float* Wo  = (const float*)d_in[11];
    const float* bo  = (const float*)d_in[12];
    float* out = (float*)d_out;

    __half *A16, *X16, *Wi16, *Ws, *h016, *comb;
    float *embs, *ps, *bc;
    cudaGetSymbolAddress((void**)&A16,   g_A16);
    cudaGetSymbolAddress((void**)&X16,   g_X16);
    cudaGetSymbolAddress((void**)&Wi16,  g_Wi16);
    cudaGetSymbolAddress((void**)&Ws,    g_Ws);
    cudaGetSymbolAddress((void**)&h016,  g_h016);
    cudaGetSymbolAddress((void**)&comb,  g_comb);
    cudaGetSymbolAddress((void**)&embs,  g_embs);
    cudaGetSymbolAddress((void**)&ps,    g_ps);
    cudaGetSymbolAddress((void**)&bc,    g_bc);

    cudaFuncSetAttribute(gemm_big, cudaFuncAttributeMaxDynamicSharedMemorySize, GB_SMEM);
    cudaFuncSetAttribute(gemm_cvt, cudaFuncAttributeMaxDynamicSharedMemorySize, GC_SMEM);

    // 1. fp16 conversions + fused-weight precompute
    f2h<<<(NN * IND / 4 + 255) / 256, 256>>>(nf, X16, NN * IND / 4);
    f2h<<<(IND * HH / 4 + 255) / 256, 256>>>((const float*)d_in[2], Wi16, IND * HH / 4);
    fuse_w<<<dim3(2 * HH + 1, NL), HH>>>((const float*)d_in[4], (const float*)d_in[6],
                                          (const float*)d_in[5], (const float*)d_in[7]);

    // 2. h0 = X @ Wi + bi  (fp16 out)
    gemm_k<<<128, 256>>>(X16, IND, Wi16, HH,
                         nullptr, 0, h016, HH, bi, nullptr, IND, 0);

    // 3. message passing
    for (int net = 0; net < NNET; net++) {
        copy_h0<<<(NN * HH / 8 + 255) / 256, 256>>>();
        for (int l = 0; l < NL; l++) {
            if (l == 0) {
                // fused: convert fp32 adj -> fp16 (cache in g_A16) + rowsums + SpMM vs h0
                gemm_cvt<<<dim3(NN / 128, 2), 256, GC_SMEM>>>(
                    adj + (size_t)net * NN * NN, h016, HH, ps);
                combine0<<<NN * HH / 4 / 256, 256>>>();
            } else {
                gemm_big<<<dim3(NN / 128, 2), 256, GB_SMEM>>>(A16, comb, 2 * HH, ps);
                combine_k<<<NN * HH / 4 / 256, 256>>>();
            }
            // h = relu([h|msg] @ Ws[l] + bc[l]) -> comb[:,0:128] (+fp32 embs if last)
            float* c32 = (l == NL - 1) ? (embs + (size_t)net * NN * HH) : nullptr;
            gemm_k<<<128, 256>>>(comb, 2 * HH, Ws + (size_t)l * 2 * HH * HH, HH,
                                 c32, HH, comb, 2 * HH,
                                 bc + l * HH, nullptr, 2 * HH, 1);
        }
    }

    // 4. cross-layer attention + output projection
    attn_out<<<NN / 32, 256>>>(Wa, ba, v, Wo, bo, out);

    // 5. deterministic mean over nodes
    mean_part<<<128, 128>>>(out);
    mean_fin<<<1, 128>>>(out + (size_t)NN * HH);
}

// round 10
// speedup vs baseline: 1.0277x; 1.0084x over previous
#include <cuda_runtime.h>
#include <cuda_fp16.h>
#include <mma.h>
#include <cstdint>
#include <cstddef>

using namespace nvcuda;

#define NN    8192
#define IND   256
#define HH    128
#define NL    3
#define NNET  3

// ---------------- device scratch (static, allowed) ----------------
__device__ __align__(16) __half g_A16[(size_t)NN * NN];          // one net's fp16 adj (134 MB)
__device__ __align__(16) __half g_X16[NN * IND];
__device__ __align__(16) __half g_Wi16[IND * HH];
__device__ __align__(16) __half g_Ws[NL * 2 * HH * HH];          // fused [Wu_top; Wm@Wu_bot]
__device__ float g_bc[NL * HH];                                   // fused bias
__device__ __align__(16) __half g_h016[NN * HH];
__device__ __align__(16) __half g_comb[NN * 2 * HH];             // [h | msg]
__device__ __align__(16) float g_ps[2 * NN * HH];                // split-K fp32 partials
__device__ float g_degp[2 * NN];                                  // split-K degree partials
__device__ float g_invdeg[NN];                                    // current net's 1/deg
__device__ float g_embs[(size_t)NNET * NN * HH];                 // per-net final layer embeddings
__device__ float g_part[128 * HH];

// ---------------- helpers ----------------
__device__ __forceinline__ uint32_t s2u(const void* p){
    uint32_t a;
    asm("{ .reg .u64 t; cvta.to.shared.u64 t, %1; cvt.u32.u64 %0, t; }" : "=r"(a) : "l"(p));
    return a;
}
__device__ __forceinline__ void cp16(uint32_t dst, const void* src){
    asm volatile("cp.async.cg.shared.global [%0], [%1], 16;" :: "r"(dst), "l"(src));
}
#define CP_COMMIT() asm volatile("cp.async.commit_group;" ::: "memory")
#define CP_WAIT4()  asm volatile("cp.async.wait_group 4;" ::: "memory")

// =================== pipelined SpMM (layers 1-2): part = A16 @ B ===================
// grid (64, 2). 6-stage cp.async pipeline, BK=64, 8 warps each computing 32x64.
#define GB_S    6
#define GB_ASZ  (128 * 72 * 2)                  // 18432 B
#define GB_BSZ  (64 * 136 * 2)                  // 17408 B
#define GB_STG  (GB_ASZ + GB_BSZ)               // 35840 B
#define GB_SMEM (GB_S * GB_STG)                 // 215040 B

__global__ __launch_bounds__(256, 1) void gemm_big(
    const __half* __restrict__ A,
    const __half* __restrict__ B, int ldb,
    float* __restrict__ part)
{
    extern __shared__ char dsm[];
    uint32_t sb = s2u(dsm);
    int tid = threadIdx.x;
    int wid = tid >> 5;
    int bm = blockIdx.x * 128;
    int kbase = blockIdx.y * 4096;
    int wm = (wid >> 1) * 32;
    int wn = (wid & 1) * 64;

    auto load_stage = [&](int st, int kt) {
        int k0 = kbase + kt * 64;
        uint32_t abase = sb + st * GB_STG;
        uint32_t bbase = abase + GB_ASZ;
#pragma unroll
        for (int i = 0; i < 4; i++) {
            int idx = tid + i * 256;
            int r = idx >> 3, c = idx & 7;
            cp16(abase + r * 144 + c * 16,
                 A + (size_t)(bm + r) * NN + k0 + c * 8);
        }
#pragma unroll
        for (int i = 0; i < 4; i++) {
            int idx = tid + i * 256;
            int r = idx >> 4, c = idx & 15;
            cp16(bbase + r * 272 + c * 16,
                 B + (size_t)(k0 + r) * ldb + c * 8);
        }
    };

    wmma::fragment<wmma::accumulator, 16, 16, 16, float> acc[2][4];
#pragma unroll
    for (int i = 0; i < 2; i++)
#pragma unroll
        for (int j = 0; j < 4; j++)
            wmma::fill_fragment(acc[i][j], 0.0f);

#pragma unroll
    for (int s = 0; s < GB_S - 1; s++) { load_stage(s, s); CP_COMMIT(); }

    const int nk = 4096 / 64;
    int st_use = 0, st_load = GB_S - 1;
    for (int kt = 0; kt < nk; kt++) {
        CP_WAIT4();
        __syncthreads();
        if (kt + GB_S - 1 < nk) load_stage(st_load, kt + GB_S - 1);
        CP_COMMIT();

        const __half* pA = reinterpret_cast<const __half*>(dsm + st_use * GB_STG);
        const __half* pB = reinterpret_cast<const __half*>(dsm + st_use * GB_STG + GB_ASZ);
#pragma unroll
        for (int kk = 0; kk < 64; kk += 16) {
            wmma::fragment<wmma::matrix_a, 16, 16, 16, __half, wmma::row_major> fa[2];
            wmma::fragment<wmma::matrix_b, 16, 16, 16, __half, wmma::row_major> fb[4];
#pragma unroll
            for (int i = 0; i < 2; i++)
                wmma::load_matrix_sync(fa[i], pA + (size_t)(wm + 16 * i) * 72 + kk, 72);
#pragma unroll
            for (int j = 0; j < 4; j++)
                wmma::load_matrix_sync(fb[j], pB + (size_t)kk * 136 + wn + 16 * j, 136);
#pragma unroll
            for (int i = 0; i < 2; i++)
#pragma unroll
                for (int j = 0; j < 4; j++)
                    wmma::mma_sync(acc[i][j], fa[i], fb[j], acc[i][j]);
        }
        __syncthreads();
        if (++st_use == GB_S) st_use = 0;
        if (++st_load == GB_S) st_load = 0;
    }

    float* sC = reinterpret_cast<float*>(dsm);     // 128 x 132
#pragma unroll
    for (int i = 0; i < 2; i++)
#pragma unroll
        for (int j = 0; j < 4; j++)
            wmma::store_matrix_sync(sC + (size_t)(wm + 16 * i) * 132 + wn + 16 * j,
                                    acc[i][j], 132, wmma::mem_row_major);
    __syncthreads();

    float* out = part + (size_t)blockIdx.y * NN * HH + (size_t)bm * HH;
    for (int e = tid; e < 128 * 128 / 4; e += 256) {
        int r = e >> 5, c = (e & 31) * 4;
        *reinterpret_cast<float4*>(out + (size_t)r * HH + c) =
            *reinterpret_cast<const float4*>(sC + (size_t)r * 132 + c);
    }
}

// ====== fused layer-0 SpMM: reads fp32 adj, converts->fp16 (emit g_A16), rowsums, MMA ======
// grid (64, 2). 6-stage pipeline, BK=32: fp32 staging -> fp16 smem -> HMMA.
#define GC_S     6
#define GC_A32   (128 * 36 * 4)                 // 18432 B (pad 36 floats/row)
#define GC_A16   (128 * 40 * 2)                 // 10240 B (pad 40 halves/row)
#define GC_B16   (32 * 136 * 2)                 //  8704 B
#define GC_STG   (GC_A32 + GC_A16 + GC_B16)     // 37376 B
#define GC_SMEM  (GC_S * GC_STG)                // 224256 B

__global__ __launch_bounds__(256, 1) void gemm_cvt(
    const float* __restrict__ A32,              // raw adj for this net [NN x NN] fp32
    const __half* __restrict__ B, int ldb,
    float* __restrict__ part)
{
    extern __shared__ char dsm[];
    uint32_t sb = s2u(dsm);
    int tid = threadIdx.x;
    int wid = tid >> 5;
    int bm = blockIdx.x * 128;
    int kbase = blockIdx.y * 4096;
    int wm = (wid >> 1) * 32;
    int wn = (wid & 1) * 64;

    auto load_stage = [&](int st, int kt) {
        int k0 = kbase + kt * 32;
        uint32_t a32b = sb + st * GC_STG;
        uint32_t b16b = a32b + GC_A32 + GC_A16;
#pragma unroll
        for (int i = 0; i < 4; i++) {           // A fp32: 128 rows x 32 floats (128B/row)
            int idx = tid + i * 256;
            int r = idx >> 3, c = idx & 7;      // c: 16B = 4 floats
            cp16(a32b + r * 144 + c * 16,
                 A32 + (size_t)(bm + r) * NN + k0 + c * 4);
        }
#pragma unroll
        for (int i = 0; i < 2; i++) {           // B fp16: 32 rows x 128 halves (256B/row)
            int idx = tid + i * 256;
            int r = idx >> 4, c = idx & 15;
            cp16(b16b + r * 272 + c * 16,
                 B + (size_t)(k0 + r) * ldb + c * 8);
        }
    };

    wmma::fragment<wmma::accumulator, 16, 16, 16, float> acc[2][4];
#pragma unroll
    for (int i = 0; i < 2; i++)
#pragma unroll
        for (int j = 0; j < 4; j++)
            wmma::fill_fragment(acc[i][j], 0.0f);

#pragma unroll
    for (int s = 0; s < GC_S - 1; s++) { load_stage(s, s); CP_COMMIT(); }

    // per-thread convert coords: row = tid/2, 16-float half (tid&1)
    int crow = tid >> 1;
    int ccol = (tid & 1) * 16;
    float rsum = 0.f;

    const int nk = 4096 / 32;
    int st_use = 0, st_load = GC_S - 1;
    for (int kt = 0; kt < nk; kt++) {
        CP_WAIT4();
        __syncthreads();
        if (kt + GC_S - 1 < nk) load_stage(st_load, kt + GC_S - 1);
        CP_COMMIT();

        char* stg = dsm + st_use * GC_STG;
        const float* pA32 = reinterpret_cast<const float*>(stg);         // ld 36
        __half* pA16 = reinterpret_cast<__half*>(stg + GC_A32);          // ld 40
        const __half* pB = reinterpret_cast<const __half*>(stg + GC_A32 + GC_A16);

        // ---- convert my 16 floats: fp32 smem -> fp16 smem + STG to g_A16 + rowsum ----
        {
            int k0 = kbase + kt * 32;
            float lsum = 0.f;
#pragma unroll
            for (int j = 0; j < 2; j++) {
                float4 f0 = *reinterpret_cast<const float4*>(pA32 + (size_t)crow * 36 + ccol + j * 8);
                float4 f1 = *reinterpret_cast<const float4*>(pA32 + (size_t)crow * 36 + ccol + j * 8 + 4);
                lsum += ((f0.x + f0.y) + (f0.z + f0.w)) + ((f1.x + f1.y) + (f1.z + f1.w));
                __half2 h0 = __floats2half2_rn(f0.x, f0.y);
                __half2 h1 = __floats2half2_rn(f0.z, f0.w);
                __half2 h2 = __floats2half2_rn(f1.x, f1.y);
                __half2 h3 = __floats2half2_rn(f1.z, f1.w);
                uint4 u;
                u.x = *reinterpret_cast<unsigned*>(&h0);
                u.y = *reinterpret_cast<unsigned*>(&h1);
                u.z = *reinterpret_cast<unsigned*>(&h2);
                u.w = *reinterpret_cast<unsigned*>(&h3);
                *reinterpret_cast<uint4*>(pA16 + (size_t)crow * 40 + ccol + j * 8) = u;
                *reinterpret_cast<uint4*>(g_A16 + (size_t)(bm + crow) * NN + k0 + ccol + j * 8) = u;
            }
            float other = __shfl_xor_sync(0xFFFFFFFFu, lsum, 1);
            if ((tid & 1) == 0) rsum += lsum + other;
        }
        __syncthreads();

        // ---- HMMA on converted tile ----
#pragma unroll
        for (int kk = 0; kk < 32; kk += 16) {
            wmma::fragment<wmma::matrix_a, 16, 16, 16, __half, wmma::row_major> fa[2];
            wmma::fragment<wmma::matrix_b, 16, 16, 16, __half, wmma::row_major> fb[4];
#pragma unroll
            for (int i = 0; i < 2; i++)
                wmma::load_matrix_sync(fa[i], pA16 + (size_t)(wm + 16 * i) * 40 + kk, 40);
#pragma unroll
            for (int j = 0; j < 4; j++)
                wmma::load_matrix_sync(fb[j], pB + (size_t)kk * 136 + wn + 16 * j, 136);
#pragma unroll
            for (int i = 0; i < 2; i++)
#pragma unroll
                for (int j = 0; j < 4; j++)
                    wmma::mma_sync(acc[i][j], fa[i], fb[j], acc[i][j]);
        }
        if (++st_use == GC_S) st_use = 0;
        if (++st_load == GC_S) st_load = 0;
    }

    // degree partials (one writer per row)
    if ((tid & 1) == 0)
        g_degp[(size_t)blockIdx.y * NN + bm + crow] = rsum;

    __syncthreads();
    float* sC = reinterpret_cast<float*>(dsm);     // 128 x 132
#pragma unroll
    for (int i = 0; i < 2; i++)
#pragma unroll
        for (int j = 0; j < 4; j++)
            wmma::store_matrix_sync(sC + (size_t)(wm + 16 * i) * 132 + wn + 16 * j,
                                    acc[i][j], 132, wmma::mem_row_major);
    __syncthreads();

    float* out = part + (size_t)blockIdx.y * NN * HH + (size_t)bm * HH;
    for (int e = tid; e < 128 * 128 / 4; e += 256) {
        int r = e >> 5, c = (e & 31) * 4;
        *reinterpret_cast<float4*>(out + (size_t)r * HH + c) =
            *reinterpret_cast<const float4*>(sC + (size_t)r * 132 + c);
    }
}

// ---- layer-0 combine: inv = 1/max(deg,1); comb[:,128:256] = (p0+p1)*inv; store invdeg ----
__global__ void combine0()
{
    int i = blockIdx.x * 256 + threadIdx.x;       // float4 group
    int n = i >> 5, coff = (i & 31) * 4;
    float d = g_degp[n] + g_degp[NN + n];
    float s = 1.0f / fmaxf(d, 1.0f);
    if ((i & 31) == 0) g_invdeg[n] = s;
    const float4* p = reinterpret_cast<const float4*>(g_ps);
    float4 a = p[i], b = p[i + NN * HH / 4];
    __half2 h0 = __floats2half2_rn((a.x + b.x) * s, (a.y + b.y) * s);
    __half2 h1 = __floats2half2_rn((a.z + b.z) * s, (a.w + b.w) * s);
    uint2 u;
    u.x = *reinterpret_cast<unsigned*>(&h0);
    u.y = *reinterpret_cast<unsigned*>(&h1);
    *reinterpret_cast<uint2*>(g_comb + (size_t)n * 256 + 128 + coff) = u;
}

// ---- layers 1-2 combine: comb[:,128:256] = (p0+p1)*invdeg ----
__global__ void combine_k()
{
    int i = blockIdx.x * 256 + threadIdx.x;
    int n = i >> 5, coff = (i & 31) * 4;
    float s = g_invdeg[n];
    const float4* p = reinterpret_cast<const float4*>(g_ps);
    float4 a = p[i], b = p[i + NN * HH / 4];
    __half2 h0 = __floats2half2_rn((a.x + b.x) * s, (a.y + b.y) * s);
    __half2 h1 = __floats2half2_rn((a.z + b.z) * s, (a.w + b.w) * s);
    uint2 u;
    u.x = *reinterpret_cast<unsigned*>(&h0);
    u.y = *reinterpret_cast<unsigned*>(&h1);
    *reinterpret_cast<uint2*>(g_comb + (size_t)n * 256 + 128 + coff) = u;
}

// ---------------- generic fp32 -> fp16 convert ----------------
__global__ void f2h(const float* __restrict__ src, __half* __restrict__ dst, int n4)
{
    int i = blockIdx.x * blockDim.x + threadIdx.x;
    if (i < n4) {
        float4 f = reinterpret_cast<const float4*>(src)[i];
        __half2 a = __floats2half2_rn(f.x, f.y);
        __half2 b = __floats2half2_rn(f.z, f.w);
        uint2 u;
        u.x = *reinterpret_cast<unsigned*>(&a);
        u.y = *reinterpret_cast<unsigned*>(&b);
        *reinterpret_cast<uint2*>(dst + (size_t)i * 4) = u;
    }
}

// ------- fused weight precompute: Ws[l] = [Wu_top ; Wm[l]@Wu_bot], bc[l] = bm@Wu_bot + bu -------
__global__ void fuse_w(const float* __restrict__ Wm, const float* __restrict__ Wu,
                       const float* __restrict__ bm, const float* __restrict__ bu)
{
    int l = blockIdx.y;
    int r = blockIdx.x;          // 0..256
    int j = threadIdx.x;         // 128
    const float* WuL = Wu + (size_t)l * 2 * HH * HH;   // [256][128]
    if (r < HH) {
        g_Ws[((size_t)l * 256 + r) * HH + j] = __float2half(WuL[(size_t)r * HH + j]);
    } else if (r < 2 * HH) {
        int rr = r - HH;
        __shared__ float wm[HH];
        wm[j] = Wm[((size_t)l * HH + rr) * HH + j];
        __syncthreads();
        float acc = 0.f;
#pragma unroll 8
        for (int k = 0; k < HH; k++)
            acc += wm[k] * WuL[(size_t)(HH + k) * HH + j];
        g_Ws[((size_t)l * 256 + r) * HH + j] = __float2half(acc);
    } else {
        __shared__ float bb[HH];
        bb[j] = bm[l * HH + j];
        __syncthreads();
        float acc = bu[l * HH + j];
#pragma unroll 8
        for (int k = 0; k < HH; k++)
            acc += bb[k] * WuL[(size_t)(HH + k) * HH + j];
        g_bc[l * HH + j] = acc;
    }
}

// ---------------- comb[:,0:128] = h0_16 ----------------
__global__ void copy_h0()
{
    int i = blockIdx.x * 256 + threadIdx.x;
    if (i < NN * HH / 8) {
        int n = i >> 4;
        int c = (i & 15) * 8;
        *reinterpret_cast<float4*>(g_comb + (size_t)n * 256 + c) =
            *reinterpret_cast<const float4*>(g_h016 + (size_t)n * 128 + c);
    }
}

// ---------------- fp16 wmma GEMM (small K: projections/updates) ----------------
__global__ __launch_bounds__(256) void gemm_k(
    const __half* __restrict__ A, int lda,
    const __half* __restrict__ B, int ldb,
    float* __restrict__ C32, int ldc32,
    __half* __restrict__ C16, int ldc16,
    const float* __restrict__ bias,
    const float* __restrict__ rowscale,
    int K, int relu)
{
    constexpr int BM = 64, BN = 128, BK = 64;
    __shared__ __align__(16) char sraw[33792];
    __half (*sA)[BK + 8] = reinterpret_cast<__half(*)[BK + 8]>(sraw);
    __half (*sB)[BN + 8] = reinterpret_cast<__half(*)[BN + 8]>(sraw + 9216);
    float* sC = reinterpret_cast<float*>(sraw);

    int tid = threadIdx.x;
    int wid = tid >> 5;
    int bm = blockIdx.x * BM;
    int wm = (wid >> 2) * 32;
    int wn = (wid & 3) * 32;

    wmma::fragment<wmma::accumulator, 16, 16, 16, float> acc[2][2];
#pragma unroll
    for (int i = 0; i < 2; i++)
#pragma unroll
        for (int j = 0; j < 2; j++)
            wmma::fill_fragment(acc[i][j], 0.0f);

    float4 ra[2], rb[4];
#pragma unroll
    for (int i = 0; i < 2; i++) {
        int idx = tid * 8 + i * 2048;
        ra[i] = *reinterpret_cast<const float4*>(A + (size_t)(bm + (idx >> 6)) * lda + (idx & 63));
    }
#pragma unroll
    for (int i = 0; i < 4; i++) {
        int idx = tid * 8 + i * 2048;
        rb[i] = *reinterpret_cast<const float4*>(B + (size_t)(idx >> 7) * ldb + (idx & 127));
    }

    int nk = K >> 6;
    for (int kt = 0; kt < nk; kt++) {
#pragma unroll
        for (int i = 0; i < 2; i++) {
            int idx = tid * 8 + i * 2048;
            *reinterpret_cast<float4*>(&sA[idx >> 6][idx & 63]) = ra[i];
        }
#pragma unroll
        for (int i = 0; i < 4; i++) {
            int idx = tid * 8 + i * 2048;
            *reinterpret_cast<float4*>(&sB[idx >> 7][idx & 127]) = rb[i];
        }
        __syncthreads();

        if (kt + 1 < nk) {
            int k0 = (kt + 1) << 6;
#pragma unroll
            for (int i = 0; i < 2; i++) {
                int idx = tid * 8 + i * 2048;
                ra[i] = *reinterpret_cast<const float4*>(A + (size_t)(bm + (idx >> 6)) * lda + k0 + (idx & 63));
            }
#pragma unroll
            for (int i = 0; i < 4; i++) {
                int idx = tid * 8 + i * 2048;
                rb[i] = *reinterpret_cast<const float4*>(B + (size_t)(k0 + (idx >> 7)) * ldb + (idx & 127));
            }
        }

#pragma unroll
        for (int kk = 0; kk < BK; kk += 16) {
            wmma::fragment<wmma::matrix_a, 16, 16, 16, __half, wmma::row_major> fa[2];
            wmma::fragment<wmma::matrix_b, 16, 16, 16, __half, wmma::row_major> fb[2];
            wmma::load_matrix_sync(fa[0], &sA[wm][kk], BK + 8);
            wmma::load_matrix_sync(fa[1], &sA[wm + 16][kk], BK + 8);
            wmma::load_matrix_sync(fb[0], &sB[kk][wn], BN + 8);
            wmma::load_matrix_sync(fb[1], &sB[kk][wn + 16], BN + 8);
#pragma unroll
            for (int i = 0; i < 2; i++)
#pragma unroll
                for (int j = 0; j < 2; j++)
                    wmma::mma_sync(acc[i][j], fa[i], fb[j], acc[i][j]);
        }
        __syncthreads();
    }

#pragma unroll
    for (int i = 0; i < 2; i++)
#pragma unroll
        for (int j = 0; j < 2; j++)
            wmma::store_matrix_sync(sC + (size_t)(wm + 16 * i) * 132 + (wn + 16 * j),
                                    acc[i][j], 132, wmma::mem_row_major);
    __syncthreads();

    for (int e = tid; e < BM * BN; e += 256) {
        int r = e >> 7, c = e & 127;
        float vv = sC[r * 132 + c];
        if (rowscale) vv *= rowscale[bm + r];
        if (bias) vv += bias[c];
        if (relu) vv = fmaxf(vv, 0.0f);
        if (C16) C16[(size_t)(bm + r) * ldc16 + c] = __float2half(vv);
        if (C32) C32[(size_t)(bm + r) * ldc32 + c] = vv;
    }
}

// ---------------- attention over layers + output projection ----------------
__global__ __launch_bounds__(256) void attn_out(
    const float* __restrict__ Wa, const float* __restrict__ ba,
    const float* __restrict__ v, const float* __restrict__ Wo,
    const float* __restrict__ bo, float* __restrict__ out)
{
    __shared__ float sWa[HH * 4];
    __shared__ float sba[4], sv[4];
    __shared__ float smix[8][4][132];
    int t = threadIdx.x;
    for (int i = t; i < HH * 4; i += 256) sWa[i] = Wa[i];
    if (t < 4) { sba[t] = ba[t]; sv[t] = v[t]; }
    __syncthreads();

    int w = t >> 5, lane = t & 31;
    for (int q = 0; q < 4; q++) {
        int n = blockIdx.x * 32 + w * 4 + q;
        float e[3][4];
#pragma unroll
        for (int l = 0; l < 3; l++)
#pragma unroll
            for (int ii = 0; ii < 4; ii++)
                e[l][ii] = g_embs[((size_t)l * NN + n) * HH + lane + 32 * ii];

        float sc[3];
#pragma unroll
        for (int l = 0; l < 3; l++) {
            float s = 0.f;
#pragma unroll
            for (int hd = 0; hd < 4; hd++) {
                float d = 0.f;
#pragma unroll
                for (int ii = 0; ii < 4; ii++)
                    d += e[l][ii] * sWa[(lane + 32 * ii) * 4 + hd];
#pragma unroll
                for (int o = 16; o; o >>= 1) d += __shfl_xor_sync(0xFFFFFFFFu, d, o);
                s += tanhf(d + sba[hd]) * sv[hd];
            }
            sc[l] = s;
        }
        float mx = fmaxf(sc[0], fmaxf(sc[1], sc[2]));
        float w0 = expf(sc[0] - mx), w1 = expf(sc[1] - mx), w2 = expf(sc[2] - mx);
        float inv = 1.0f / (w0 + w1 + w2);
        w0 *= inv; w1 *= inv; w2 *= inv;
#pragma unroll
        for (int ii = 0; ii < 4; ii++)
            smix[w][q][lane + 32 * ii] = w0 * e[0][ii] + w1 * e[1][ii] + w2 * e[2][ii];
        __syncwarp();
#pragma unroll
        for (int jj = 0; jj < 4; jj++) {
            int j = lane + 32 * jj;
            float a = bo[j];
            for (int h = 0; h < HH; h++)
                a += smix[w][q][h] * Wo[h * HH + j];
            out[(size_t)n * HH + j] = a;
        }
        __syncwarp();
    }
}

// ---------------- deterministic mean reduction ----------------
__global__ void mean_part(const float* __restrict__ out)
{
    int b = blockIdx.x;
    int t = threadIdx.x;
    float s = 0.f;
    for (int r = 0; r < 64; r++)
        s += out[((size_t)b * 64 + r) * HH + t];
    g_part[b * HH + t] = s;
}
__global__ void mean_fin(float* __restrict__ gout)
{
    int t = threadIdx.x;
    float s = 0.f;
    for (int i = 0; i < 128; i++) s += g_part[i * HH + t];
    gout[t] = s * (1.0f / (float)NN);
}

// ---------------- launcher ----------------
extern "C" void kernel_launch(void* const* d_in, const int* in_sizes, int n_in,
                              void* d_out, int out_size)
{
    (void)in_sizes; (void)n_in; (void)out_size;
    const float* nf  = (const float*)d_in[0];
    const float* adj = (const float*)d_in[1];
    const float* bi  = (const float*)d_in[3];
    const float* Wa  = (const float*)d_in[8];
    const float* ba  = (const float*)d_in[9];
    const float* v   = (const float*)d_in[10];
    const float* Wo  = (const float*)d_in[11];
    const float* bo  = (const float*)d_in[12];
    float* out = (float*)d_out;

    __half *A16, *X16, *Wi16, *Ws, *h016, *comb;
    float *embs, *ps, *bc;
    cudaGetSymbolAddress((void**)&A16,   g_A16);
    cudaGetSymbolAddress((void**)&X16,   g_X16);
    cudaGetSymbolAddress((void**)&Wi16,  g_Wi16);
    cudaGetSymbolAddress((void**)&Ws,    g_Ws);
    cudaGetSymbolAddress((void**)&h016,  g_h016);
    cudaGetSymbolAddress((void**)&comb,  g_comb);
    cudaGetSymbolAddress((void**)&embs,  g_embs);
    cudaGetSymbolAddress((void**)&ps,    g_ps);
    cudaGetSymbolAddress((void**)&bc,    g_bc);

    cudaFuncSetAttribute(gemm_big, cudaFuncAttributeMaxDynamicSharedMemorySize, GB_SMEM);
    cudaFuncSetAttribute(gemm_cvt, cudaFuncAttributeMaxDynamicSharedMemorySize, GC_SMEM);

    // 1. fp16 conversions + fused-weight precompute
    f2h<<<(NN * IND / 4 + 255) / 256, 256>>>(nf, X16, NN * IND / 4);
    f2h<<<(IND * HH / 4 + 255) / 256, 256>>>((const float*)d_in[2], Wi16, IND * HH / 4);
    fuse_w<<<dim3(2 * HH + 1, NL), HH>>>((const float*)d_in[4], (const float*)d_in[6],
                                          (const float*)d_in[5], (const float*)d_in[7]);

    // 2. h0 = X @ Wi + bi  (fp16 out)
    gemm_k<<<128, 256>>>(X16, IND, Wi16, HH,
                         nullptr, 0, h016, HH, bi, nullptr, IND, 0);

    // 3. message passing
    for (int net = 0; net < NNET; net++) {
        copy_h0<<<(NN * HH / 8 + 255) / 256, 256>>>();
        for (int l = 0; l < NL; l++) {
            if (l == 0) {
                // fused: convert fp32 adj -> fp16 (cache in g_A16) + rowsums + SpMM vs h0
                gemm_cvt<<<dim3(NN / 128, 2), 256, GC_SMEM>>>(
                    adj + (size_t)net * NN * NN, h016, HH, ps);
                combine0<<<NN * HH / 4 / 256, 256>>>();
            } else {
                gemm_big<<<dim3(NN / 128, 2), 256, GB_SMEM>>>(A16, comb, 2 * HH, ps);
                combine_k<<<NN * HH / 4 / 256, 256>>>();
            }
            // h = relu([h|msg] @ Ws[l] + bc[l]) -> comb[:,0:128] (+fp32 embs if last)
            float* c32 = (l == NL - 1) ? (embs + (size_t)net * NN * HH) : nullptr;
            gemm_k<<<128, 256>>>(comb, 2 * HH, Ws + (size_t)l * 2 * HH * HH, HH,
                                 c32, HH, comb, 2 * HH,
                                 bc + l * HH, nullptr, 2 * HH, 1);
        }
    }

    // 4. cross-layer attention + output projection
    attn_out<<<NN / 32, 256>>>(Wa, ba, v, Wo, bo, out);

    // 5. deterministic mean over nodes
    mean_part<<<128, 128>>>(out);
    mean_fin<<<1, 128>>>(out + (size_t)NN * HH);
}

// round 13
// speedup vs baseline: 1.0429x; 1.0149x over previous
#include <cuda_runtime.h>
#include <cuda_fp16.h>
#include <mma.h>
#include <cstdint>
#include <cstddef>

using namespace nvcuda;

#define NN    8192
#define IND   256
#define HH    128
#define NL    3
#define NNET  3

// ---------------- device scratch (static, allowed) ----------------
__device__ __align__(16) __half g_A16[2][(size_t)NN * NN];       // double-buffered fp16 adj (2x134 MB)
__device__ __align__(16) __half g_X16[NN * IND];
__device__ __align__(16) __half g_Wi16[IND * HH];
__device__ __align__(16) __half g_Ws[NL * 2 * HH * HH];          // fused [Wu_top; Wm@Wu_bot]
__device__ float g_bc[NL * HH];                                   // fused bias
__device__ __align__(16) __half g_h016[NN * HH];
__device__ __align__(16) __half g_comb[NN * 2 * HH];             // [h | msg]
__device__ __align__(16) float g_ps[2 * NN * HH];                // split-K fp32 partials
__device__ float g_invdeg[NNET * NN];                             // per-net 1/deg
__device__ float g_embs[(size_t)NNET * NN * HH];                 // per-net final layer embeddings
__device__ float g_part[128 * HH];

// ---------------- helpers ----------------
__device__ __forceinline__ uint32_t s2u(const void* p){
    uint32_t a;
    asm("{ .reg .u64 t; cvta.to.shared.u64 t, %1; cvt.u32.u64 %0, t; }" : "=r"(a) : "l"(p));
    return a;
}
__device__ __forceinline__ void cp16(uint32_t dst, const void* src){
    asm volatile("cp.async.cg.shared.global [%0], [%1], 16;" :: "r"(dst), "l"(src));
}
#define CP_COMMIT() asm volatile("cp.async.commit_group;" ::: "memory")
#define CP_WAIT4()  asm volatile("cp.async.wait_group 4;" ::: "memory")

// =================== pipelined SpMM: part = A16 @ B (fp32 partials) ===================
// grid (64, 2). 6-stage cp.async pipeline, BK=64, 8 warps each computing 32x64.
#define GB_S    6
#define GB_ASZ  (128 * 72 * 2)                  // 18432 B
#define GB_BSZ  (64 * 136 * 2)                  // 17408 B
#define GB_STG  (GB_ASZ + GB_BSZ)               // 35840 B
#define GB_SMEM (GB_S * GB_STG)                 // 215040 B

__global__ __launch_bounds__(256, 1) void gemm_big(
    const __half* __restrict__ A,
    const __half* __restrict__ B, int ldb,
    float* __restrict__ part)
{
    extern __shared__ char dsm[];
    uint32_t sb = s2u(dsm);
    int tid = threadIdx.x;
    int wid = tid >> 5;
    int bm = blockIdx.x * 128;
    int kbase = blockIdx.y * 4096;
    int wm = (wid >> 1) * 32;
    int wn = (wid & 1) * 64;

    auto load_stage = [&](int st, int kt) {
        int k0 = kbase + kt * 64;
        uint32_t abase = sb + st * GB_STG;
        uint32_t bbase = abase + GB_ASZ;
#pragma unroll
        for (int i = 0; i < 4; i++) {
            int idx = tid + i * 256;
            int r = idx >> 3, c = idx & 7;
            cp16(abase + r * 144 + c * 16,
                 A + (size_t)(bm + r) * NN + k0 + c * 8);
        }
#pragma unroll
        for (int i = 0; i < 4; i++) {
            int idx = tid + i * 256;
            int r = idx >> 4, c = idx & 15;
            cp16(bbase + r * 272 + c * 16,
                 B + (size_t)(k0 + r) * ldb + c * 8);
        }
    };

    wmma::fragment<wmma::accumulator, 16, 16, 16, float> acc[2][4];
#pragma unroll
    for (int i = 0; i < 2; i++)
#pragma unroll
        for (int j = 0; j < 4; j++)
            wmma::fill_fragment(acc[i][j], 0.0f);

#pragma unroll
    for (int s = 0; s < GB_S - 1; s++) { load_stage(s, s); CP_COMMIT(); }

    const int nk = 4096 / 64;
    int st_use = 0, st_load = GB_S - 1;
    for (int kt = 0; kt < nk; kt++) {
        CP_WAIT4();
        __syncthreads();
        if (kt + GB_S - 1 < nk) load_stage(st_load, kt + GB_S - 1);
        CP_COMMIT();

        const __half* pA = reinterpret_cast<const __half*>(dsm + st_use * GB_STG);
        const __half* pB = reinterpret_cast<const __half*>(dsm + st_use * GB_STG + GB_ASZ);
#pragma unroll
        for (int kk = 0; kk < 64; kk += 16) {
            wmma::fragment<wmma::matrix_a, 16, 16, 16, __half, wmma::row_major> fa[2];
            wmma::fragment<wmma::matrix_b, 16, 16, 16, __half, wmma::row_major> fb[4];
#pragma unroll
            for (int i = 0; i < 2; i++)
                wmma::load_matrix_sync(fa[i], pA + (size_t)(wm + 16 * i) * 72 + kk, 72);
#pragma unroll
            for (int j = 0; j < 4; j++)
                wmma::load_matrix_sync(fb[j], pB + (size_t)kk * 136 + wn + 16 * j, 136);
#pragma unroll
            for (int i = 0; i < 2; i++)
#pragma unroll
                for (int j = 0; j < 4; j++)
                    wmma::mma_sync(acc[i][j], fa[i], fb[j], acc[i][j]);
        }
        __syncthreads();
        if (++st_use == GB_S) st_use = 0;
        if (++st_load == GB_S) st_load = 0;
    }

    float* sC = reinterpret_cast<float*>(dsm);     // 128 x 132
#pragma unroll
    for (int i = 0; i < 2; i++)
#pragma unroll
        for (int j = 0; j < 4; j++)
            wmma::store_matrix_sync(sC + (size_t)(wm + 16 * i) * 132 + wn + 16 * j,
                                    acc[i][j], 132, wmma::mem_row_major);
    __syncthreads();

    float* out = part + (size_t)blockIdx.y * NN * HH + (size_t)bm * HH;
    for (int e = tid; e < 128 * 128 / 4; e += 256) {
        int r = e >> 5, c = (e & 31) * 4;
        *reinterpret_cast<float4*>(out + (size_t)r * HH + c) =
            *reinterpret_cast<const float4*>(sC + (size_t)r * 132 + c);
    }
}

// ---------------- adj fp32 -> fp16 + row-sum (one pass, pure-BW) ----------------
__global__ void prep_adj(const float* __restrict__ src0,
                         __half* __restrict__ dst0,
                         float* __restrict__ invdeg)
{
    size_t row = blockIdx.x;                 // 0..NN-1
    const float* src = src0 + row * NN;
    __half* dst = dst0 + row * NN;
    int t = threadIdx.x;                     // 256
    float s = 0.f;
#pragma unroll
    for (int i = 0; i < 8; i++) {
        int v4 = t + i * 256;
        float4 f = *reinterpret_cast<const float4*>(src + (size_t)v4 * 4);
        s += f.x + f.y + f.z + f.w;
        __half2 h0 = __floats2half2_rn(f.x, f.y);
        __half2 h1 = __floats2half2_rn(f.z, f.w);
        uint2 u;
        u.x = *reinterpret_cast<unsigned*>(&h0);
        u.y = *reinterpret_cast<unsigned*>(&h1);
        *reinterpret_cast<uint2*>(dst + (size_t)v4 * 4) = u;
    }
#pragma unroll
    for (int o = 16; o; o >>= 1) s += __shfl_xor_sync(0xFFFFFFFFu, s, o);
    __shared__ float ws[8];
    int wid = t >> 5, lane = t & 31;
    if (lane == 0) ws[wid] = s;
    __syncthreads();
    if (t == 0) {
        float tot = 0.f;
#pragma unroll
        for (int i = 0; i < 8; i++) tot += ws[i];
        invdeg[row] = 1.0f / fmaxf(tot, 1.0f);
    }
}

// ---- combine split-K partials: comb[:,128:256] = (p0+p1)*invdeg (fp16) ----
__global__ void combine_k(const float* __restrict__ inv)
{
    int i = blockIdx.x * 256 + threadIdx.x;       // float4 group
    int n = i >> 5, coff = (i & 31) * 4;
    float s = inv[n];
    const float4* p = reinterpret_cast<const float4*>(g_ps);
    float4 a = p[i], b = p[i + NN * HH / 4];
    __half2 h0 = __floats2half2_rn((a.x + b.x) * s, (a.y + b.y) * s);
    __half2 h1 = __floats2half2_rn((a.z + b.z) * s, (a.w + b.w) * s);
    uint2 u;
    u.x = *reinterpret_cast<unsigned*>(&h0);
    u.y = *reinterpret_cast<unsigned*>(&h1);
    *reinterpret_cast<uint2*>(g_comb + (size_t)n * 256 + 128 + coff) = u;
}

// ---------------- generic fp32 -> fp16 convert ----------------
__global__ void f2h(const float* __restrict__ src, __half* __restrict__ dst, int n4)
{
    int i = blockIdx.x * blockDim.x + threadIdx.x;
    if (i < n4) {
        float4 f = reinterpret_cast<const float4*>(src)[i];
        __half2 a = __floats2half2_rn(f.x, f.y);
        __half2 b = __floats2half2_rn(f.z, f.w);
        uint2 u;
        u.x = *reinterpret_cast<unsigned*>(&a);
        u.y = *reinterpret_cast<unsigned*>(&b);
        *reinterpret_cast<uint2*>(dst + (size_t)i * 4) = u;
    }
}

// ------- fused weight precompute: Ws[l] = [Wu_top ; Wm[l]@Wu_bot], bc[l] = bm@Wu_bot + bu -------
__global__ void fuse_w(const float* __restrict__ Wm, const float* __restrict__ Wu,
                       const float* __restrict__ bm, const float* __restrict__ bu)
{
    int l = blockIdx.y;
    int r = blockIdx.x;          // 0..256
    int j = threadIdx.x;         // 128
    const float* WuL = Wu + (size_t)l * 2 * HH * HH;   // [256][128]
    if (r < HH) {
        g_Ws[((size_t)l * 256 + r) * HH + j] = __float2half(WuL[(size_t)r * HH + j]);
    } else if (r < 2 * HH) {
        int rr = r - HH;
        __shared__ float wm[HH];
        wm[j] = Wm[((size_t)l * HH + rr) * HH + j];
        __syncthreads();
        float acc = 0.f;
#pragma unroll 8
        for (int k = 0; k < HH; k++)
            acc += wm[k] * WuL[(size_t)(HH + k) * HH + j];
        g_Ws[((size_t)l * 256 + r) * HH + j] = __float2half(acc);
    } else {
        __shared__ float bb[HH];
        bb[j] = bm[l * HH + j];
        __syncthreads();
        float acc = bu[l * HH + j];
#pragma unroll 8
        for (int k = 0; k < HH; k++)
            acc += bb[k] * WuL[(size_t)(HH + k) * HH + j];
        g_bc[l * HH + j] = acc;
    }
}

// ---------------- comb[:,0:128] = h0_16 ----------------
__global__ void copy_h0()
{
    int i = blockIdx.x * 256 + threadIdx.x;
    if (i < NN * HH / 8) {
        int n = i >> 4;
        int c = (i & 15) * 8;
        *reinterpret_cast<float4*>(g_comb + (size_t)n * 256 + c) =
            *reinterpret_cast<const float4*>(g_h016 + (size_t)n * 128 + c);
    }
}

// -------- fp16 wmma GEMM, BM=32 (grid 256 -> better occupancy for small-K GEMMs) --------
__global__ __launch_bounds__(256) void gemm_k(
    const __half* __restrict__ A, int lda,
    const __half* __restrict__ B, int ldb,
    float* __restrict__ C32, int ldc32,
    __half* __restrict__ C16, int ldc16,
    const float* __restrict__ bias,
    int K, int relu)
{
    constexpr int BM = 32, BN = 128, BK = 64;
    __shared__ __align__(16) char sraw[22016];    // sA 32x72x2=4608, sB 64x136x2=17408
    __half (*sA)[BK + 8] = reinterpret_cast<__half(*)[BK + 8]>(sraw);
    __half (*sB)[BN + 8] = reinterpret_cast<__half(*)[BN + 8]>(sraw + 4608);
    float* sC = reinterpret_cast<float*>(sraw);   // 32x132 f32 = 16896 B

    int tid = threadIdx.x;
    int wid = tid >> 5;
    int bm = blockIdx.x * BM;
    int wm = (wid >> 2) * 16;
    int wn = (wid & 3) * 32;

    wmma::fragment<wmma::accumulator, 16, 16, 16, float> acc[2];
#pragma unroll
    for (int j = 0; j < 2; j++) wmma::fill_fragment(acc[j], 0.0f);

    float4 ra, rb[4];
    {
        int idx = tid * 8;
        ra = *reinterpret_cast<const float4*>(A + (size_t)(bm + (idx >> 6)) * lda + (idx & 63));
#pragma unroll
        for (int i = 0; i < 4; i++) {
            int bidx = tid * 8 + i * 2048;
            rb[i] = *reinterpret_cast<const float4*>(B + (size_t)(bidx >> 7) * ldb + (bidx & 127));
        }
    }

    int nk = K >> 6;
    for (int kt = 0; kt < nk; kt++) {
        {
            int idx = tid * 8;
            *reinterpret_cast<float4*>(&sA[idx >> 6][idx & 63]) = ra;
#pragma unroll
            for (int i = 0; i < 4; i++) {
                int bidx = tid * 8 + i * 2048;
                *reinterpret_cast<float4*>(&sB[bidx >> 7][bidx & 127]) = rb[i];
            }
        }
        __syncthreads();

        if (kt + 1 < nk) {
            int k0 = (kt + 1) << 6;
            int idx = tid * 8;
            ra = *reinterpret_cast<const float4*>(A + (size_t)(bm + (idx >> 6)) * lda + k0 + (idx & 63));
#pragma unroll
            for (int i = 0; i < 4; i++) {
                int bidx = tid * 8 + i * 2048;
                rb[i] = *reinterpret_cast<const float4*>(B + (size_t)(k0 + (bidx >> 7)) * ldb + (bidx & 127));
            }
        }

#pragma unroll
        for (int kk = 0; kk < BK; kk += 16) {
            wmma::fragment<wmma::matrix_a, 16, 16, 16, __half, wmma::row_major> fa;
            wmma::fragment<wmma::matrix_b, 16, 16, 16, __half, wmma::row_major> fb[2];
            wmma::load_matrix_sync(fa, &sA[wm][kk], BK + 8);
            wmma::load_matrix_sync(fb[0], &sB[kk][wn], BN + 8);
            wmma::load_matrix_sync(fb[1], &sB[kk][wn + 16], BN + 8);
#pragma unroll
            for (int j = 0; j < 2; j++)
                wmma::mma_sync(acc[j], fa, fb[j], acc[j]);
        }
        __syncthreads();
    }

#pragma unroll
    for (int j = 0; j < 2; j++)
        wmma::store_matrix_sync(sC + (size_t)wm * 132 + (wn + 16 * j),
                                acc[j], 132, wmma::mem_row_major);
    __syncthreads();

    for (int e = tid; e < BM * BN; e += 256) {
        int r = e >> 7, c = e & 127;
        float vv = sC[r * 132 + c];
        if (bias) vv += bias[c];
        if (relu) vv = fmaxf(vv, 0.0f);
        if (C16) C16[(size_t)(bm + r) * ldc16 + c] = __float2half(vv);
        if (C32) C32[(size_t)(bm + r) * ldc32 + c] = vv;
    }
}

// ---------------- attention over layers + output projection ----------------
__global__ __launch_bounds__(256) void attn_out(
    const float* __restrict__ Wa, const float* __restrict__ ba,
    const float* __restrict__ v, const float* __restrict__ Wo,
    const float* __restrict__ bo, float* __restrict__ out)
{
    __shared__ float sWa[HH * 4];
    __shared__ float sba[4], sv[4];
    __shared__ float smix[8][4][132];
    int t = threadIdx.x;
    for (int i = t; i < HH * 4; i += 256) sWa[i] = Wa[i];
    if (t < 4) { sba[t] = ba[t]; sv[t] = v[t]; }
    __syncthreads();

    int w = t >> 5, lane = t & 31;
    for (int q = 0; q < 4; q++) {
        int n = blockIdx.x * 32 + w * 4 + q;
        float e[3][4];
#pragma unroll
        for (int l = 0; l < 3; l++)
#pragma unroll
            for (int ii = 0; ii < 4; ii++)
                e[l][ii] = g_embs[((size_t)l * NN + n) * HH + lane + 32 * ii];

        float sc[3];
#pragma unroll
        for (int l = 0; l < 3; l++) {
            float s = 0.f;
#pragma unroll
            for (int hd = 0; hd < 4; hd++) {
                float d = 0.f;
#pragma unroll
                for (int ii = 0; ii < 4; ii++)
                    d += e[l][ii] * sWa[(lane + 32 * ii) * 4 + hd];
#pragma unroll
                for (int o = 16; o; o >>= 1) d += __shfl_xor_sync(0xFFFFFFFFu, d, o);
                s += tanhf(d + sba[hd]) * sv[hd];
            }
            sc[l] = s;
        }
        float mx = fmaxf(sc[0], fmaxf(sc[1], sc[2]));
        float w0 = expf(sc[0] - mx), w1 = expf(sc[1] - mx), w2 = expf(sc[2] - mx);
        float inv = 1.0f / (w0 + w1 + w2);
        w0 *= inv; w1 *= inv; w2 *= inv;
#pragma unroll
        for (int ii = 0; ii < 4; ii++)
            smix[w][q][lane + 32 * ii] = w0 * e[0][ii] + w1 * e[1][ii] + w2 * e[2][ii];
        __syncwarp();
#pragma unroll
        for (int jj = 0; jj < 4; jj++) {
            int j = lane + 32 * jj;
            float a = bo[j];
            for (int h = 0; h < HH; h++)
                a += smix[w][q][h] * Wo[h * HH + j];
            out[(size_t)n * HH + j] = a;
        }
        __syncwarp();
    }
}

// ---------------- deterministic mean reduction ----------------
__global__ void mean_part(const float* __restrict__ out)
{
    int b = blockIdx.x;
    int t = threadIdx.x;
    float s = 0.f;
    for (int r = 0; r < 64; r++)
        s += out[((size_t)b * 64 + r) * HH + t];
    g_part[b * HH + t] = s;
}
__global__ void mean_fin(float* __restrict__ gout)
{
    int t = threadIdx.x;
    float s = 0.f;
    for (int i = 0; i < 128; i++) s += g_part[i * HH + t];
    gout[t] = s * (1.0f / (float)NN);
}

// ---------------- launcher ----------------
extern "C" void kernel_launch(void* const* d_in, const int* in_sizes, int n_in,
                              void* d_out, int out_size)
{
    (void)in_sizes; (void)n_in; (void)out_size;
    const float* nf  = (const float*)d_in[0];
    const float* adj = (const float*)d_in[1];
    const float* bi  = (const float*)d_in[3];
    const float* Wa  = (const float*)d_in[8];
    const float* ba  = (const float*)d_in[9];
    const float* v   = (const float*)d_in[10];
    const float* Wo  = (const float*)d_in[11];
    const float* bo  = (const float*)d_in[12];
    float* out = (float*)d_out;

    __half *A16, *X16, *Wi16, *Ws, *h016, *comb;
    float *invdeg, *embs, *ps, *bc;
    cudaGetSymbolAddress((void**)&A16,   g_A16);
    cudaGetSymbolAddress((void**)&X16,   g_X16);
    cudaGetSymbolAddress((void**)&Wi16,  g_Wi16);
    cudaGetSymbolAddress((void**)&Ws,    g_Ws);
    cudaGetSymbolAddress((void**)&h016,  g_h016);
    cudaGetSymbolAddress((void**)&comb,  g_comb);
    cudaGetSymbolAddress((void**)&invdeg, g_invdeg);
    cudaGetSymbolAddress((void**)&embs,  g_embs);
    cudaGetSymbolAddress((void**)&ps,    g_ps);
    cudaGetSymbolAddress((void**)&bc,    g_bc);

    cudaFuncSetAttribute(gemm_big, cudaFuncAttributeMaxDynamicSharedMemorySize, GB_SMEM);

    // side stream + events for overlapping prep_adj(net+1) with net-k compute.
    // kernel_launch runs only for the correctness call + the single capture call,
    // so per-call create (no destroy) leaks at most a couple of host handles.
    cudaStream_t s = 0;
    if (cudaStreamCreateWithFlags(&s, cudaStreamNonBlocking) != cudaSuccess) s = 0;
    cudaEvent_t e0, eF[2], eP[3];
    cudaEventCreateWithFlags(&e0, cudaEventDisableTiming);
    for (int i = 0; i < 2; i++) cudaEventCreateWithFlags(&eF[i], cudaEventDisableTiming);
    for (int i = 0; i < 3; i++) cudaEventCreateWithFlags(&eP[i], cudaEventDisableTiming);

    // fork: prep net 0 into buffer 0 on side stream
    cudaEventRecord(e0, 0);
    cudaStreamWaitEvent(s, e0, 0);
    prep_adj<<<NN, 256, 0, s>>>(adj, A16, invdeg);
    cudaEventRecord(eP[0], s);

    // main: small prep work (overlaps prep_adj net 0)
    f2h<<<(NN * IND / 4 + 255) / 256, 256>>>(nf, X16, NN * IND / 4);
    f2h<<<(IND * HH / 4 + 255) / 256, 256>>>((const float*)d_in[2], Wi16, IND * HH / 4);
    fuse_w<<<dim3(2 * HH + 1, NL), HH>>>((const float*)d_in[4], (const float*)d_in[6],
                                          (const float*)d_in[5], (const float*)d_in[7]);
    gemm_k<<<256, 256>>>(X16, IND, Wi16, HH,
                         nullptr, 0, h016, HH, bi, IND, 0);

    // message passing; prep of net+1 overlaps net's compute chain (disjoint A16 buffer)
    for (int net = 0; net < NNET; net++) {
        int buf = net & 1;
        cudaStreamWaitEvent(0, eP[net], 0);          // A16[buf] ready
        if (net + 1 < NNET) {
            cudaEventRecord(eF[net & 1], 0);         // main done reading A16[buf^1]
            cudaStreamWaitEvent(s, eF[net & 1], 0);
            prep_adj<<<NN, 256, 0, s>>>(adj + (size_t)(net + 1) * NN * NN,
                                        A16 + (size_t)((net + 1) & 1) * NN * NN,
                                        invdeg + (net + 1) * NN);
            cudaEventRecord(eP[net + 1], s);
        }
        copy_h0<<<(NN * HH / 8 + 255) / 256, 256>>>();
        for (int l = 0; l < NL; l++) {
            const __half* Bsrc = (l == 0) ? h016 : comb;
            int ldb = (l == 0) ? HH : 2 * HH;
            gemm_big<<<dim3(NN / 128, 2), 256, GB_SMEM>>>(
                A16 + (size_t)buf * NN * NN, Bsrc, ldb, ps);
            combine_k<<<NN * HH / 4 / 256, 256>>>(invdeg + net * NN);
            float* c32 = (l == NL - 1) ? (embs + (size_t)net * NN * HH) : nullptr;
            gemm_k<<<256, 256>>>(comb, 2 * HH, Ws + (size_t)l * 2 * HH * HH, HH,
                                 c32, HH, comb, 2 * HH,
                                 bc + l * HH, 2 * HH, 1);
        }
    }

    // cross-layer attention + output projection
    attn_out<<<NN / 32, 256>>>(Wa, ba, v, Wo, bo, out);

    // deterministic mean over nodes
    mean_part<<<128, 128>>>(out);
    mean_fin<<<1, 128>>>(out + (size_t)NN * HH);
}